// round 8
// baseline (speedup 1.0000x reference)
#include <cuda_runtime.h>
#include <cuda_bf16.h>
#include <math.h>
#include <stdint.h>

// ---------------------------------------------------------------- constants
#define TOTAL_ELEMS (16*256*1024)
#define N_CODES 4096
#define E_DIM   256
#define N_VECS  16384
#define DECAYF  0.99f
#define OMDF    0.01f
#define BETAF   0.25f
#define EPSF    1e-5f

#define OFF_LOSS 0
#define OFF_ZQ   1
#define OFF_PERP (1 + TOTAL_ELEMS)
#define OFF_IDX  (2 + TOTAL_ELEMS)
#define OFF_EMB  (2 + TOTAL_ELEMS + N_VECS)
#define OFF_CS   (OFF_EMB + N_CODES*E_DIM)
#define OFF_EA   (OFF_CS + N_CODES)

// Phase-1 GEMM geometry: block = 128 rows x 256-code chunks (16 chunks),
// single bf16 split (a0*b0). 8 warps, warp tile 64x64.
#define M_BLK 128
#define N_CHUNK 256
#define N_CHUNKS 16
#define N_TILES (N_CHUNKS * 8)      // 8 k-tiles of 32 per chunk

#define CAND_CAP 64

// smem layout (bytes from base)
#define A_STRIDE 528                // 256 bf16 = 512B + 16 pad (ldmatrix conflict-free)
#define SOFF_A     0                // 128 x 528 = 67584
#define SOFF_B     67584            // 2 bufs x 256*80 = 40960
#define SOFF_ENS   108544           // 2 bufs x 1024
#define SOFF_RED   110592           // 128*16*4 = 8192
#define SOFF_RMAX  118784           // 128*4
#define SOFF_MARG  119296           // 128*4
#define SMEM_TOTAL 119808

// ---------------------------------------------------------------- scratch
__device__ __align__(128) __nv_bfloat16 g_zs0[(size_t)N_VECS * E_DIM];
__device__ __align__(128) __nv_bfloat16 g_es0[(size_t)N_CODES * E_DIM];
__device__ __align__(128) float g_zfT[(size_t)N_VECS * E_DIM];   // fp32, n-major
__device__ __align__(128) float g_zn2[N_VECS];                   // ||z_n||^2
__device__ __align__(128) float g_enorm[N_CODES];
__device__ __align__(128) int   g_idx[N_VECS];
__device__ __align__(128) int   g_ccnt[N_VECS];
__device__ __align__(128) float g_cval[(size_t)N_VECS * CAND_CAP];
__device__ __align__(128) int   g_cidx[(size_t)N_VECS * CAND_CAP];
__device__ __align__(128) float g_enc_sum[N_CODES];
__device__ __align__(128) float g_embed_sum[N_CODES * E_DIM];
__device__ float g_loss;
__device__ float g_n;
__device__ float g_bmax;

// ---------------------------------------------------------------- asm helpers
__device__ __forceinline__ uint32_t smem_u32(const void* p) {
    uint32_t a;
    asm("{ .reg .u64 t; cvta.to.shared.u64 t, %1; cvt.u32.u64 %0, t; }" : "=r"(a) : "l"(p));
    return a;
}
#define CP16(dst, src)   asm volatile("cp.async.cg.shared.global [%0], [%1], 16;" :: "r"(dst), "l"(src) : "memory")
#define CP_COMMIT()      asm volatile("cp.async.commit_group;" ::: "memory")
#define CP_WAIT1()       asm volatile("cp.async.wait_group 1;" ::: "memory")
#define CP_WAIT0()       asm volatile("cp.async.wait_group 0;" ::: "memory")

#define LDSM_X4(r, addr) asm volatile( \
    "ldmatrix.sync.aligned.m8n8.x4.shared.b16 {%0,%1,%2,%3}, [%4];" \
    : "=r"((r)[0]),"=r"((r)[1]),"=r"((r)[2]),"=r"((r)[3]) : "r"(addr))
#define LDSM_X2(r, addr) asm volatile( \
    "ldmatrix.sync.aligned.m8n8.x2.shared.b16 {%0,%1}, [%2];" \
    : "=r"((r)[0]),"=r"((r)[1]) : "r"(addr))

#define MMA16816(c, a, b) asm volatile( \
    "mma.sync.aligned.m16n8k16.row.col.f32.bf16.bf16.f32 " \
    "{%0,%1,%2,%3}, {%4,%5,%6,%7}, {%8,%9}, {%0,%1,%2,%3};" \
    : "+f"((c)[0]),"+f"((c)[1]),"+f"((c)[2]),"+f"((c)[3]) \
    : "r"((a)[0]),"r"((a)[1]),"r"((a)[2]),"r"((a)[3]), "r"((b)[0]),"r"((b)[1]))

// ---------------------------------------------------------------- prep kernels
__global__ void k_zero() {
    int t = blockIdx.x * blockDim.x + threadIdx.x;
    int nt = gridDim.x * blockDim.x;
    for (int i = t; i < N_CODES * E_DIM; i += nt) g_embed_sum[i] = 0.f;
    for (int i = t; i < N_CODES; i += nt) g_enc_sum[i] = 0.f;
    for (int i = t; i < N_VECS; i += nt) { g_ccnt[i] = 0; g_zn2[i] = 0.f; }
    if (t == 0) { g_loss = 0.f; g_bmax = 0.f; }
}

__global__ void k_enorm(const float* __restrict__ emb) {
    int warp = (blockIdx.x * blockDim.x + threadIdx.x) >> 5;
    int lane = threadIdx.x & 31;
    if (warp >= N_CODES) return;
    const float* r = emb + warp * E_DIM;
    float s = 0.f;
    #pragma unroll
    for (int c = 0; c < E_DIM; c += 32) { float v = r[c + lane]; s += v * v; }
    #pragma unroll
    for (int o = 16; o; o >>= 1) s += __shfl_down_sync(0xffffffffu, s, o);
    if (lane == 0) {
        g_enorm[warp] = 0.5f * s;
        atomicMax((int*)&g_bmax, __float_as_int(sqrtf(s)));   // positive floats
    }
}

// z (b, c, p) -> g_zs0 bf16, g_zfT fp32 [n][k]; accumulate ||z_n||^2
__global__ void k_split_z(const float* __restrict__ z) {
    __shared__ float t[32][33];
    int b  = blockIdx.z;
    int c0 = blockIdx.y * 32;
    int p0 = blockIdx.x * 32;
    #pragma unroll
    for (int i = 0; i < 32; i += 8)
        t[threadIdx.y + i][threadIdx.x] =
            z[((size_t)(b * 256 + c0 + threadIdx.y + i)) * 1024 + p0 + threadIdx.x];
    __syncthreads();
    #pragma unroll
    for (int i = 0; i < 32; i += 8) {
        int n = b * 1024 + p0 + threadIdx.y + i;
        int k = c0 + threadIdx.x;
        float v = t[threadIdx.x][threadIdx.y + i];
        size_t o = (size_t)n * E_DIM + k;
        g_zs0[o] = __float2bfloat16(v);
        g_zfT[o] = v;
        float s = v * v;
        #pragma unroll
        for (int of = 16; of; of >>= 1) s += __shfl_down_sync(0xffffffffu, s, of);
        if (threadIdx.x == 0) atomicAdd(g_zn2 + n, s);
    }
}

__global__ void k_split_e(const float* __restrict__ emb) {
    int i = blockIdx.x * blockDim.x + threadIdx.x;
    if (i >= N_CODES * E_DIM) return;
    g_es0[i] = __float2bfloat16(emb[i]);
}

// ---------------------------------------------------------------- phase 1: approx GEMM + candidate collect
__global__ __launch_bounds__(256) void k_mma() {
    extern __shared__ char smem_raw[];
    const uint32_t SB = smem_u32(smem_raw);
    const int tid  = threadIdx.x;
    const int lane = tid & 31;
    const int wid  = tid >> 5;
    const int warp_m = wid >> 2;        // 0..1
    const int warp_n = wid & 3;         // 0..3
    const int m0 = blockIdx.x * M_BLK;

    const int a_row = warp_m * 64 + ((lane >> 3) & 1) * 8 + (lane & 7);
    const uint32_t a_res_off = (uint32_t)(a_row * A_STRIDE + ((lane >> 4) & 1) * 16);
    const int lb = lane & 15;
    const uint32_t b_off = (uint32_t)((warp_n * 64 + (lb & 7)) * 80 + ((lb >> 3) & 1) * 16);

    float* redmax  = (float*)(smem_raw + SOFF_RED);
    float* rowMax  = (float*)(smem_raw + SOFF_RMAX);
    float* rowMarg = (float*)(smem_raw + SOFF_MARG);

    // tile tt: chunk = tt>>3, kt = tt&7, buf = tt&1
    auto issue_tile = [&](int tt) {
        int kt    = tt & 7;
        int chunk = tt >> 3;
        int buf   = tt & 1;
        #pragma unroll
        for (int i = 0; i < 4; ++i) {
            int li = tid + i * 256;          // 0..1023
            int code = li >> 2, seg = li & 3;
            const char* src = (const char*)(g_es0
                + (size_t)(chunk * N_CHUNK + code) * E_DIM + kt * 32 + seg * 8);
            CP16(SB + SOFF_B + buf * 20480 + code * 80 + seg * 16, src);
        }
        if (kt == 0 && tid < 64) {           // ens for this chunk
            const char* src = (const char*)(g_enorm + chunk * N_CHUNK + tid * 4);
            CP16(SB + SOFF_ENS + (chunk & 1) * 1024 + tid * 16, src);
        }
        CP_COMMIT();
    };

    // A panel (bf16) resident
    #pragma unroll
    for (int i = 0; i < 16; ++i) {
        int li = tid + i * 256;              // 0..4095
        int row = li >> 5, seg = li & 31;
        const char* src = (const char*)(g_zs0 + (size_t)(m0 + row) * E_DIM + seg * 8);
        CP16(SB + SOFF_A + row * A_STRIDE + seg * 16, src);
    }
    CP_COMMIT();

    // per-row margin (2*bf16 error bound + slack) and running max init
    if (tid < M_BLK) {
        rowMarg[tid] = 0.0158f * sqrtf(g_zn2[m0 + tid]) * g_bmax + 0.25f;
        rowMax[tid]  = -1e30f;
    }

    issue_tile(0);
    issue_tile(1);

    float acc[4][8][4];
    #pragma unroll
    for (int mt = 0; mt < 4; ++mt)
        #pragma unroll
        for (int nt = 0; nt < 8; ++nt)
            #pragma unroll
            for (int j = 0; j < 4; ++j) acc[mt][nt][j] = 0.f;

    for (int tt = 0; tt < N_TILES; ++tt) {
        if (tt == N_TILES - 1) CP_WAIT0(); else CP_WAIT1();
        __syncthreads();

        int kt  = tt & 7;
        int buf = tt & 1;
        uint32_t bbase = SB + SOFF_B + buf * 20480 + b_off;

        #pragma unroll
        for (int km = 0; km < 2; ++km) {
            uint32_t bf[8][2];
            #pragma unroll
            for (int nt = 0; nt < 8; ++nt)
                LDSM_X2(bf[nt], bbase + nt * 640 + km * 32);
            #pragma unroll
            for (int mt = 0; mt < 4; ++mt) {
                uint32_t af[4];
                LDSM_X4(af, SB + SOFF_A + a_res_off
                            + mt * (16 * A_STRIDE) + kt * 64 + km * 32);
                #pragma unroll
                for (int nt = 0; nt < 8; ++nt)
                    MMA16816(acc[mt][nt], af, bf[nt]);
            }
        }
        __syncthreads();
        if (tt + 2 < N_TILES) issue_tile(tt + 2);

        if (kt == 7) {
            // ---- chunk epilogue: scores, per-row running max, candidate insert ----
            int chunk = tt >> 3;
            const float* ens = (const float*)(smem_raw + SOFF_ENS + (chunk & 1) * 1024);

            // convert acc -> score values in place; per-slot maxes
            float smax[8];
            #pragma unroll
            for (int s = 0; s < 8; ++s) smax[s] = -1e30f;
            #pragma unroll
            for (int mt = 0; mt < 4; ++mt)
                #pragma unroll
                for (int nt = 0; nt < 8; ++nt)
                    #pragma unroll
                    for (int j = 0; j < 4; ++j) {
                        int cl = warp_n * 64 + nt * 8 + (lane & 3) * 2 + (j & 1);
                        float v = acc[mt][nt][j] - ens[cl];
                        acc[mt][nt][j] = v;
                        int slot = mt * 2 + (j >> 1);
                        smax[slot] = fmaxf(smax[slot], v);
                    }
            // per-row reduction of slot maxes
            #pragma unroll
            for (int s = 0; s < 8; ++s) {
                int mt = s >> 1, half = s & 1;
                int row = warp_m * 64 + mt * 16 + half * 8 + (lane >> 2);
                redmax[row * 16 + warp_n * 4 + (lane & 3)] = smax[s];
            }
            __syncthreads();
            if (tid < M_BLK) {
                float m = redmax[tid * 16];
                #pragma unroll
                for (int t = 1; t < 16; ++t) m = fmaxf(m, redmax[tid * 16 + t]);
                rowMax[tid] = fmaxf(rowMax[tid], m);
            }
            __syncthreads();
            // insertion: v >= rowMax - margin
            #pragma unroll
            for (int mt = 0; mt < 4; ++mt) {
                #pragma unroll
                for (int jh = 0; jh < 2; ++jh) {
                    int row = warp_m * 64 + mt * 16 + jh * 8 + (lane >> 2);
                    float thr = rowMax[row] - rowMarg[row];
                    int n = m0 + row;
                    #pragma unroll
                    for (int nt = 0; nt < 8; ++nt)
                        #pragma unroll
                        for (int jl = 0; jl < 2; ++jl) {
                            float v = acc[mt][nt][jh * 2 + jl];
                            if (v >= thr) {
                                int pos = atomicAdd(g_ccnt + n, 1);
                                if (pos < CAND_CAP) {
                                    g_cval[(size_t)n * CAND_CAP + pos] = v;
                                    g_cidx[(size_t)n * CAND_CAP + pos] =
                                        chunk * N_CHUNK + warp_n * 64 + nt * 8 + (lane & 3) * 2 + jl;
                                }
                            }
                            acc[mt][nt][jh * 2 + jl] = 0.f;
                        }
                }
            }
        }
    }
}

// ---------------------------------------------------------------- phase 2: exact rescore of candidates
__global__ __launch_bounds__(256) void k_refine(const float* __restrict__ emb,
                                                float* __restrict__ dout) {
    __shared__ float zsm[8][256];
    int w = threadIdx.x >> 5;
    int lane = threadIdx.x & 31;
    int n = blockIdx.x * 8 + w;
    if (n >= N_VECS) return;

    float zr[8];
    float an2 = 0.f;
    #pragma unroll
    for (int j = 0; j < 8; ++j) {
        zr[j] = g_zfT[(size_t)n * E_DIM + lane + 32 * j];
        an2 += zr[j] * zr[j];
    }
    #pragma unroll
    for (int o = 16; o; o >>= 1) an2 += __shfl_xor_sync(0xffffffffu, an2, o);
    float margin = 0.0158f * sqrtf(an2) * g_bmax + 0.25f;

    float best_v = -1e30f;
    int   best_i = 0x7fffffff;
    int cnt = g_ccnt[n];

    if (cnt <= CAND_CAP) {
        // buffer max == global approx max (max element always inserted)
        float bmx = -1e30f;
        for (int i = lane; i < cnt; i += 32)
            bmx = fmaxf(bmx, g_cval[(size_t)n * CAND_CAP + i]);
        #pragma unroll
        for (int o = 16; o; o >>= 1) bmx = fmaxf(bmx, __shfl_xor_sync(0xffffffffu, bmx, o));
        float thr = bmx - margin;

        for (int i = 0; i < cnt; ++i) {
            float av = g_cval[(size_t)n * CAND_CAP + i];   // broadcast (same per warp)
            if (av < thr) continue;
            int c = g_cidx[(size_t)n * CAND_CAP + i];
            const float* er = emb + (size_t)c * E_DIM;
            float d = 0.f;
            #pragma unroll
            for (int j = 0; j < 8; ++j)
                d = fmaf(zr[j], er[lane + 32 * j], d);
            #pragma unroll
            for (int o = 16; o; o >>= 1) d += __shfl_xor_sync(0xffffffffu, d, o);
            float sv = d - g_enorm[c];
            if (sv > best_v || (sv == best_v && c < best_i)) { best_v = sv; best_i = c; }
        }
    } else {
        // overflow fallback: exact full scan (correct, ~never taken)
        #pragma unroll
        for (int j = 0; j < 8; ++j) zsm[w][lane + 32 * j] = zr[j];
        __syncwarp();
        for (int ci = 0; ci < 128; ++ci) {
            int c = lane + 32 * (ci & 3) + 128 * (ci >> 2);  // any full cover works
            c = ci * 32 + lane;
            const float* er = emb + (size_t)c * E_DIM;
            float d = 0.f;
            for (int k = 0; k < 256; ++k) d = fmaf(zsm[w][k], er[k], d);
            float sv = d - g_enorm[c];
            if (sv > best_v || (sv == best_v && c < best_i)) { best_v = sv; best_i = c; }
        }
        // cross-lane combine with index tie-break
        #pragma unroll
        for (int o = 16; o; o >>= 1) {
            float ov = __shfl_xor_sync(0xffffffffu, best_v, o);
            int   oi = __shfl_xor_sync(0xffffffffu, best_i, o);
            if (ov > best_v || (ov == best_v && oi < best_i)) { best_v = ov; best_i = oi; }
        }
    }
    if (lane == 0) {
        g_idx[n] = best_i;
        dout[OFF_IDX + n] = (float)best_i;
    }
}

// ---------------------------------------------------------------- epilogue kernels
__global__ void k_gather(const float* __restrict__ z, const float* __restrict__ emb,
                         float* __restrict__ dout) {
    __shared__ float sred[256];
    int t  = blockIdx.x * blockDim.x + threadIdx.x;
    int nt = gridDim.x * blockDim.x;
    float ls = 0.f;
    for (int e = t; e < TOTAL_ELEMS; e += nt) {
        int p  = e & 1023;
        int c  = (e >> 10) & 255;
        int bb = e >> 18;
        int n  = (bb << 10) + p;
        int code = g_idx[n];
        float zv = z[e];
        float ev = __ldg(emb + (size_t)code * E_DIM + c);
        dout[OFF_ZQ + e] = ev;
        float d = ev - zv;
        ls += d * d;
        atomicAdd(g_embed_sum + (size_t)code * E_DIM + c, zv);
        if (c == 0) atomicAdd(g_enc_sum + code, 1.0f);
    }
    sred[threadIdx.x] = ls;
    __syncthreads();
    for (int s = 128; s; s >>= 1) {
        if (threadIdx.x < s) sred[threadIdx.x] += sred[threadIdx.x + s];
        __syncthreads();
    }
    if (threadIdx.x == 0) atomicAdd(&g_loss, sred[0]);
}

__global__ void k_fin1(const float* __restrict__ cs, float* __restrict__ dout) {
    __shared__ float sn[1024];
    __shared__ float sp[1024];
    int t = threadIdx.x;
    float ln = 0.f, lp = 0.f;
    for (int j = t; j < N_CODES; j += 1024) {
        float es  = g_enc_sum[j];
        float ncs = cs[j] * DECAYF + OMDF * es;
        dout[OFF_CS + j] = ncs;
        ln += ncs;
        float pr = es * (1.0f / (float)N_VECS);
        lp += pr * logf(pr + 1e-10f);
    }
    sn[t] = ln; sp[t] = lp;
    __syncthreads();
    for (int s = 512; s; s >>= 1) {
        if (t < s) { sn[t] += sn[t + s]; sp[t] += sp[t + s]; }
        __syncthreads();
    }
    if (t == 0) {
        g_n = sn[0];
        dout[OFF_PERP] = expf(-sp[0]);
        dout[OFF_LOSS] = g_loss * (BETAF / (float)TOTAL_ELEMS);
    }
}

__global__ void k_fin2(const float* __restrict__ ea, float* __restrict__ dout) {
    int i = blockIdx.x * blockDim.x + threadIdx.x;
    if (i >= N_CODES * E_DIM) return;
    int code = i >> 8;
    float nea = ea[i] * DECAYF + OMDF * g_embed_sum[i];
    dout[OFF_EA + i] = nea;
    float ncs = dout[OFF_CS + code];
    float n = g_n;
    float sm = (ncs + EPSF) / (n + (float)N_CODES * EPSF) * n;
    dout[OFF_EMB + i] = nea / sm;
}

// ---------------------------------------------------------------- launch
extern "C" void kernel_launch(void* const* d_in, const int* in_sizes, int n_in,
                              void* d_out, int out_size) {
    const float* z   = (const float*)d_in[0];
    const float* emb = (const float*)d_in[1];
    const float* cs  = (const float*)d_in[2];
    const float* ea  = (const float*)d_in[3];
    float* out = (float*)d_out;

    cudaFuncSetAttribute(k_mma, cudaFuncAttributeMaxDynamicSharedMemorySize, SMEM_TOTAL);

    k_zero<<<1024, 512>>>();
    k_enorm<<<512, 256>>>(emb);
    k_split_e<<<4096, 256>>>(emb);
    k_split_z<<<dim3(32, 8, 16), dim3(32, 8)>>>(z);
    k_mma<<<N_VECS / M_BLK, 256, SMEM_TOTAL>>>();
    k_refine<<<N_VECS / 8, 256>>>(emb, out);
    k_gather<<<4096, 256>>>(z, emb, out);
    k_fin1<<<1, 1024>>>(cs, out);
    k_fin2<<<4096, 256>>>(ea, out);
}

// round 11
// speedup vs baseline: 1.0613x; 1.0613x over previous
#include <cuda_runtime.h>
#include <cuda_bf16.h>
#include <cuda_fp16.h>
#include <math.h>
#include <stdint.h>

// ---------------------------------------------------------------- constants
#define TOTAL_ELEMS (16*256*1024)
#define N_CODES 4096
#define E_DIM   256
#define N_VECS  16384
#define DECAYF  0.99f
#define OMDF    0.01f
#define BETAF   0.25f
#define EPSF    1e-5f

#define OFF_LOSS 0
#define OFF_ZQ   1
#define OFF_PERP (1 + TOTAL_ELEMS)
#define OFF_IDX  (2 + TOTAL_ELEMS)
#define OFF_EMB  (2 + TOTAL_ELEMS + N_VECS)
#define OFF_CS   (OFF_EMB + N_CODES*E_DIM)
#define OFF_EA   (OFF_CS + N_CODES)

// Phase-1 GEMM geometry: block = 128 rows x 256-code chunks (16 chunks),
// single bf16 split (a0*b0). 8 warps, warp tile 64x64.
#define M_BLK 128
#define N_CHUNK 256
#define N_CHUNKS 16
#define N_TILES (N_CHUNKS * 8)      // 8 k-tiles of 32 per chunk

// smem layout (bytes from base)
#define A_STRIDE 528                // 256 bf16 = 512B + 16 pad (ldmatrix conflict-free)
#define SOFF_A    0                 // 128 x 528 = 67584
#define SOFF_B    67584             // 2 bufs x 256*80 = 40960 (reused for final reduce)
#define SOFF_ENS  108544            // 2 bufs x 1024
#define SMEM_TOTAL 110720

// ---------------------------------------------------------------- scratch
__device__ __align__(128) __nv_bfloat16 g_zs0[(size_t)N_VECS * E_DIM];
__device__ __align__(128) __nv_bfloat16 g_es0[(size_t)N_CODES * E_DIM];
__device__ __align__(128) float g_zfT[(size_t)N_VECS * E_DIM];   // fp32, n-major
__device__ __align__(128) float g_zn2[N_VECS];                   // ||z_n||^2
__device__ __align__(128) __half g_scores[(size_t)N_VECS * N_CODES];
__device__ __align__(128) float g_rowmax[N_VECS];
__device__ __align__(128) float g_enorm[N_CODES];
__device__ __align__(128) int   g_idx[N_VECS];
__device__ __align__(128) float g_enc_sum[N_CODES];
__device__ __align__(128) float g_embed_sum[N_CODES * E_DIM];
__device__ float g_loss;
__device__ float g_n;
__device__ float g_bmax;

// ---------------------------------------------------------------- asm helpers
__device__ __forceinline__ uint32_t smem_u32(const void* p) {
    uint32_t a;
    asm("{ .reg .u64 t; cvta.to.shared.u64 t, %1; cvt.u32.u64 %0, t; }" : "=r"(a) : "l"(p));
    return a;
}
#define CP16(dst, src)   asm volatile("cp.async.cg.shared.global [%0], [%1], 16;" :: "r"(dst), "l"(src) : "memory")
#define CP_COMMIT()      asm volatile("cp.async.commit_group;" ::: "memory")
#define CP_WAIT1()       asm volatile("cp.async.wait_group 1;" ::: "memory")
#define CP_WAIT0()       asm volatile("cp.async.wait_group 0;" ::: "memory")

#define LDSM_X4(r, addr) asm volatile( \
    "ldmatrix.sync.aligned.m8n8.x4.shared.b16 {%0,%1,%2,%3}, [%4];" \
    : "=r"((r)[0]),"=r"((r)[1]),"=r"((r)[2]),"=r"((r)[3]) : "r"(addr))
#define LDSM_X2(r, addr) asm volatile( \
    "ldmatrix.sync.aligned.m8n8.x2.shared.b16 {%0,%1}, [%2];" \
    : "=r"((r)[0]),"=r"((r)[1]) : "r"(addr))

#define MMA16816(c, a, b) asm volatile( \
    "mma.sync.aligned.m16n8k16.row.col.f32.bf16.bf16.f32 " \
    "{%0,%1,%2,%3}, {%4,%5,%6,%7}, {%8,%9}, {%0,%1,%2,%3};" \
    : "+f"((c)[0]),"+f"((c)[1]),"+f"((c)[2]),"+f"((c)[3]) \
    : "r"((a)[0]),"r"((a)[1]),"r"((a)[2]),"r"((a)[3]), "r"((b)[0]),"r"((b)[1]))

// ---------------------------------------------------------------- prep kernels
__global__ void k_zero() {
    int t = blockIdx.x * blockDim.x + threadIdx.x;
    int nt = gridDim.x * blockDim.x;
    for (int i = t; i < N_CODES * E_DIM; i += nt) g_embed_sum[i] = 0.f;
    for (int i = t; i < N_CODES; i += nt) g_enc_sum[i] = 0.f;
    for (int i = t; i < N_VECS; i += nt) g_zn2[i] = 0.f;
    if (t == 0) { g_loss = 0.f; g_bmax = 0.f; }
}

__global__ void k_enorm(const float* __restrict__ emb) {
    int warp = (blockIdx.x * blockDim.x + threadIdx.x) >> 5;
    int lane = threadIdx.x & 31;
    if (warp >= N_CODES) return;
    const float* r = emb + warp * E_DIM;
    float s = 0.f;
    #pragma unroll
    for (int c = 0; c < E_DIM; c += 32) { float v = r[c + lane]; s += v * v; }
    #pragma unroll
    for (int o = 16; o; o >>= 1) s += __shfl_down_sync(0xffffffffu, s, o);
    if (lane == 0) {
        g_enorm[warp] = 0.5f * s;
        atomicMax((int*)&g_bmax, __float_as_int(sqrtf(s)));   // positive floats
    }
}

// z (b, c, p) -> g_zs0 bf16, g_zfT fp32 [n][k]; accumulate ||z_n||^2
__global__ void k_split_z(const float* __restrict__ z) {
    __shared__ float t[32][33];
    int b  = blockIdx.z;
    int c0 = blockIdx.y * 32;
    int p0 = blockIdx.x * 32;
    #pragma unroll
    for (int i = 0; i < 32; i += 8)
        t[threadIdx.y + i][threadIdx.x] =
            z[((size_t)(b * 256 + c0 + threadIdx.y + i)) * 1024 + p0 + threadIdx.x];
    __syncthreads();
    #pragma unroll
    for (int i = 0; i < 32; i += 8) {
        int n = b * 1024 + p0 + threadIdx.y + i;
        int k = c0 + threadIdx.x;
        float v = t[threadIdx.x][threadIdx.y + i];
        size_t o = (size_t)n * E_DIM + k;
        g_zs0[o] = __float2bfloat16(v);
        g_zfT[o] = v;
        float s = v * v;
        #pragma unroll
        for (int of = 16; of; of >>= 1) s += __shfl_down_sync(0xffffffffu, s, of);
        if (threadIdx.x == 0) atomicAdd(g_zn2 + n, s);
    }
}

__global__ void k_split_e(const float* __restrict__ emb) {
    int i = blockIdx.x * blockDim.x + threadIdx.x;
    if (i >= N_CODES * E_DIM) return;
    g_es0[i] = __float2bfloat16(emb[i]);
}

// ---------------------------------------------------------------- phase 1: approx GEMM
// fp16 scores to gmem + per-row max tracked in REGISTERS (one reduce at end).
__global__ __launch_bounds__(256) void k_mma() {
    extern __shared__ char smem_raw[];
    const uint32_t SB = smem_u32(smem_raw);
    const int tid  = threadIdx.x;
    const int lane = tid & 31;
    const int wid  = tid >> 5;
    const int warp_m = wid >> 2;        // 0..1
    const int warp_n = wid & 3;         // 0..3
    const int m0 = blockIdx.x * M_BLK;

    const int a_row = warp_m * 64 + ((lane >> 3) & 1) * 8 + (lane & 7);
    const uint32_t a_res_off = (uint32_t)(a_row * A_STRIDE + ((lane >> 4) & 1) * 16);
    const int lb = lane & 15;
    const uint32_t b_off = (uint32_t)((warp_n * 64 + (lb & 7)) * 80 + ((lb >> 3) & 1) * 16);

    // tile tt: chunk = tt>>3, kt = tt&7, buf = tt&1
    auto issue_tile = [&](int tt) {
        int kt    = tt & 7;
        int chunk = tt >> 3;
        int buf   = tt & 1;
        #pragma unroll
        for (int i = 0; i < 4; ++i) {
            int li = tid + i * 256;          // 0..1023
            int code = li >> 2, seg = li & 3;
            const char* src = (const char*)(g_es0
                + (size_t)(chunk * N_CHUNK + code) * E_DIM + kt * 32 + seg * 8);
            CP16(SB + SOFF_B + buf * 20480 + code * 80 + seg * 16, src);
        }
        if (kt == 0 && tid < 64) {           // ens for this chunk
            const char* src = (const char*)(g_enorm + chunk * N_CHUNK + tid * 4);
            CP16(SB + SOFF_ENS + (chunk & 1) * 1024 + tid * 16, src);
        }
        CP_COMMIT();
    };

    // A panel (bf16) resident
    #pragma unroll
    for (int i = 0; i < 16; ++i) {
        int li = tid + i * 256;              // 0..4095
        int row = li >> 5, seg = li & 31;
        const char* src = (const char*)(g_zs0 + (size_t)(m0 + row) * E_DIM + seg * 8);
        CP16(SB + SOFF_A + row * A_STRIDE + seg * 16, src);
    }
    CP_COMMIT();
    issue_tile(0);
    issue_tile(1);

    float acc[4][8][4];
    #pragma unroll
    for (int mt = 0; mt < 4; ++mt)
        #pragma unroll
        for (int nt = 0; nt < 8; ++nt)
            #pragma unroll
            for (int j = 0; j < 4; ++j) acc[mt][nt][j] = 0.f;

    float smax[8];
    #pragma unroll
    for (int s = 0; s < 8; ++s) smax[s] = -1e30f;

    for (int tt = 0; tt < N_TILES; ++tt) {
        if (tt == N_TILES - 1) CP_WAIT0(); else CP_WAIT1();
        __syncthreads();

        int kt  = tt & 7;
        int buf = tt & 1;
        uint32_t bbase = SB + SOFF_B + buf * 20480 + b_off;

        #pragma unroll
        for (int km = 0; km < 2; ++km) {
            uint32_t bf[8][2];
            #pragma unroll
            for (int nt = 0; nt < 8; ++nt)
                LDSM_X2(bf[nt], bbase + nt * 640 + km * 32);
            #pragma unroll
            for (int mt = 0; mt < 4; ++mt) {
                uint32_t af[4];
                LDSM_X4(af, SB + SOFF_A + a_res_off
                            + mt * (16 * A_STRIDE) + kt * 64 + km * 32);
                #pragma unroll
                for (int nt = 0; nt < 8; ++nt)
                    MMA16816(acc[mt][nt], af, bf[nt]);
            }
        }
        __syncthreads();
        if (tt + 2 < N_TILES) issue_tile(tt + 2);

        if (kt == 7) {
            // ---- chunk epilogue: subtract enorm, track reg-max, store fp16 ----
            int chunk = tt >> 3;
            const float* ens = (const float*)(smem_raw + SOFF_ENS + (chunk & 1) * 1024);
            #pragma unroll
            for (int mt = 0; mt < 4; ++mt) {
                int row = m0 + warp_m * 64 + mt * 16 + (lane >> 2);
                #pragma unroll
                for (int nt = 0; nt < 8; ++nt) {
                    int cl = warp_n * 64 + nt * 8 + (lane & 3) * 2;
                    int col = chunk * N_CHUNK + cl;
                    float v0 = acc[mt][nt][0] - ens[cl];
                    float v1 = acc[mt][nt][1] - ens[cl + 1];
                    float v2 = acc[mt][nt][2] - ens[cl];
                    float v3 = acc[mt][nt][3] - ens[cl + 1];
                    smax[mt * 2]     = fmaxf(smax[mt * 2],     fmaxf(v0, v1));
                    smax[mt * 2 + 1] = fmaxf(smax[mt * 2 + 1], fmaxf(v2, v3));
                    *(__half2*)(g_scores + (size_t)row * N_CODES + col) =
                        __floats2half2_rn(v0, v1);
                    *(__half2*)(g_scores + (size_t)(row + 8) * N_CODES + col) =
                        __floats2half2_rn(v2, v3);
                    acc[mt][nt][0] = 0.f; acc[mt][nt][1] = 0.f;
                    acc[mt][nt][2] = 0.f; acc[mt][nt][3] = 0.f;
                }
            }
        }
    }

    // ---- single final per-row max reduction (reuse B smem) ----
    __syncthreads();
    float* redmax = (float*)(smem_raw + SOFF_B);    // 128*16 floats
    #pragma unroll
    for (int s = 0; s < 8; ++s) {
        int mt = s >> 1, half = s & 1;
        int row = warp_m * 64 + mt * 16 + half * 8 + (lane >> 2);
        redmax[row * 16 + warp_n * 4 + (lane & 3)] = smax[s];
    }
    __syncthreads();
    if (tid < M_BLK) {
        float m = redmax[tid * 16];
        #pragma unroll
        for (int t = 1; t < 16; ++t) m = fmaxf(m, redmax[tid * 16 + t]);
        g_rowmax[m0 + tid] = m;
    }
}

// ---------------------------------------------------------------- phase 2: single-pass exact rescore
// Warp per row. thr = rowmax - margin (margin = 2u*||z||*||e||max + fp16 slack).
// One pass over the fp16 score row; candidates rescored with exact fp32 dots.
__global__ __launch_bounds__(256) void k_refine(const float* __restrict__ emb,
                                                float* __restrict__ dout) {
    int w = threadIdx.x >> 5;
    int lane = threadIdx.x & 31;
    int n = blockIdx.x * 8 + w;
    if (n >= N_VECS) return;

    float zr[8];
    #pragma unroll
    for (int j = 0; j < 8; ++j)
        zr[j] = g_zfT[(size_t)n * E_DIM + lane + 32 * j];

    float margin = 0.0158f * sqrtf(g_zn2[n]) * g_bmax + 1.2f;
    float thr = g_rowmax[n] - margin;

    const __half2* sr = (const __half2*)(g_scores + (size_t)n * N_CODES);

    float best_v = -1e30f;
    int   best_i = 0x7fffffff;

    for (int i = 0; i < 64; ++i) {
        float2 v = __half22float2(sr[i * 32 + lane]);
        unsigned mb0 = __ballot_sync(0xffffffffu, v.x >= thr);
        unsigned mb1 = __ballot_sync(0xffffffffu, v.y >= thr);
        unsigned mm = mb0 | mb1;
        while (mm) {
            int l = __ffs(mm) - 1;
            mm &= mm - 1;
            #pragma unroll
            for (int e = 0; e < 2; ++e) {
                if (!((e ? mb1 : mb0) >> l & 1)) continue;
                int c = i * 64 + l * 2 + e;
                const float* er = emb + (size_t)c * E_DIM;
                float d = 0.f;
                #pragma unroll
                for (int j = 0; j < 8; ++j)
                    d = fmaf(zr[j], er[lane + 32 * j], d);
                #pragma unroll
                for (int o = 16; o; o >>= 1) d += __shfl_xor_sync(0xffffffffu, d, o);
                float sv = d - g_enorm[c];
                if (sv > best_v || (sv == best_v && c < best_i)) { best_v = sv; best_i = c; }
            }
        }
    }
    if (lane == 0) {
        g_idx[n] = best_i;
        dout[OFF_IDX + n] = (float)best_i;
    }
}

// ---------------------------------------------------------------- epilogue kernels
__global__ void k_gather(const float* __restrict__ z, const float* __restrict__ emb,
                         float* __restrict__ dout) {
    __shared__ float sred[256];
    int t  = blockIdx.x * blockDim.x + threadIdx.x;
    int nt = gridDim.x * blockDim.x;
    float ls = 0.f;
    for (int e = t; e < TOTAL_ELEMS; e += nt) {
        int p  = e & 1023;
        int c  = (e >> 10) & 255;
        int bb = e >> 18;
        int n  = (bb << 10) + p;
        int code = g_idx[n];
        float zv = z[e];
        float ev = __ldg(emb + (size_t)code * E_DIM + c);
        dout[OFF_ZQ + e] = ev;
        float d = ev - zv;
        ls += d * d;
        atomicAdd(g_embed_sum + (size_t)code * E_DIM + c, zv);
        if (c == 0) atomicAdd(g_enc_sum + code, 1.0f);
    }
    sred[threadIdx.x] = ls;
    __syncthreads();
    for (int s = 128; s; s >>= 1) {
        if (threadIdx.x < s) sred[threadIdx.x] += sred[threadIdx.x + s];
        __syncthreads();
    }
    if (threadIdx.x == 0) atomicAdd(&g_loss, sred[0]);
}

__global__ void k_fin1(const float* __restrict__ cs, float* __restrict__ dout) {
    __shared__ float sn[1024];
    __shared__ float sp[1024];
    int t = threadIdx.x;
    float ln = 0.f, lp = 0.f;
    for (int j = t; j < N_CODES; j += 1024) {
        float es  = g_enc_sum[j];
        float ncs = cs[j] * DECAYF + OMDF * es;
        dout[OFF_CS + j] = ncs;
        ln += ncs;
        float pr = es * (1.0f / (float)N_VECS);
        lp += pr * logf(pr + 1e-10f);
    }
    sn[t] = ln; sp[t] = lp;
    __syncthreads();
    for (int s = 512; s; s >>= 1) {
        if (t < s) { sn[t] += sn[t + s]; sp[t] += sp[t + s]; }
        __syncthreads();
    }
    if (t == 0) {
        g_n = sn[0];
        dout[OFF_PERP] = expf(-sp[0]);
        dout[OFF_LOSS] = g_loss * (BETAF / (float)TOTAL_ELEMS);
    }
}

__global__ void k_fin2(const float* __restrict__ ea, float* __restrict__ dout) {
    int i = blockIdx.x * blockDim.x + threadIdx.x;
    if (i >= N_CODES * E_DIM) return;
    int code = i >> 8;
    float nea = ea[i] * DECAYF + OMDF * g_embed_sum[i];
    dout[OFF_EA + i] = nea;
    float ncs = dout[OFF_CS + code];
    float n = g_n;
    float sm = (ncs + EPSF) / (n + (float)N_CODES * EPSF) * n;
    dout[OFF_EMB + i] = nea / sm;
}

// ---------------------------------------------------------------- launch
extern "C" void kernel_launch(void* const* d_in, const int* in_sizes, int n_in,
                              void* d_out, int out_size) {
    const float* z   = (const float*)d_in[0];
    const float* emb = (const float*)d_in[1];
    const float* cs  = (const float*)d_in[2];
    const float* ea  = (const float*)d_in[3];
    float* out = (float*)d_out;

    cudaFuncSetAttribute(k_mma, cudaFuncAttributeMaxDynamicSharedMemorySize, SMEM_TOTAL);

    k_zero<<<1024, 512>>>();
    k_enorm<<<512, 256>>>(emb);
    k_split_e<<<4096, 256>>>(emb);
    k_split_z<<<dim3(32, 8, 16), dim3(32, 8)>>>(z);
    k_mma<<<N_VECS / M_BLK, 256, SMEM_TOTAL>>>();
    k_refine<<<N_VECS / 8, 256>>>(emb, out);
    k_gather<<<4096, 256>>>(z, emb, out);
    k_fin1<<<1, 1024>>>(cs, out);
    k_fin2<<<4096, 256>>>(ea, out);
}

// round 12
// speedup vs baseline: 1.0706x; 1.0088x over previous
#include <cuda_runtime.h>
#include <cuda_bf16.h>
#include <cuda_fp16.h>
#include <math.h>
#include <stdint.h>

// ---------------------------------------------------------------- constants
#define TOTAL_ELEMS (16*256*1024)
#define N_CODES 4096
#define E_DIM   256
#define N_VECS  16384
#define DECAYF  0.99f
#define OMDF    0.01f
#define BETAF   0.25f
#define EPSF    1e-5f

#define OFF_LOSS 0
#define OFF_ZQ   1
#define OFF_PERP (1 + TOTAL_ELEMS)
#define OFF_IDX  (2 + TOTAL_ELEMS)
#define OFF_EMB  (2 + TOTAL_ELEMS + N_VECS)
#define OFF_CS   (OFF_EMB + N_CODES*E_DIM)
#define OFF_EA   (OFF_CS + N_CODES)

// Phase-1 GEMM: block = 64 rows x 256-code chunks (16 chunks), bf16 a0*b0.
// 8 warps, warp tile 64x32 (warp_n = wid). 2 CTAs/SM co-resident.
#define M_BLK 64
#define N_CHUNK 256
#define N_CHUNKS 16
#define N_TILES (N_CHUNKS * 8)      // 8 k-tiles of 32 per chunk

// smem layout (bytes from base)
#define A_STRIDE 528                // 256 bf16 = 512B + 16 pad (ldmatrix conflict-free)
#define SOFF_A    0                 // 64 x 528 = 33792
#define SOFF_B    33792             // 2 bufs x 256*80 = 40960 (reused for final reduce)
#define SOFF_ENS  74752             // 2 bufs x 1024
#define SMEM_TOTAL 76800            // x2 CTAs = 153.6KB <= 228KB/SM

// ---------------------------------------------------------------- scratch
__device__ __align__(128) __nv_bfloat16 g_zs0[(size_t)N_VECS * E_DIM];
__device__ __align__(128) __nv_bfloat16 g_es0[(size_t)N_CODES * E_DIM];
__device__ __align__(128) float g_zfT[(size_t)N_VECS * E_DIM];   // fp32, n-major
__device__ __align__(128) float g_zn2[N_VECS];                   // ||z_n||^2
__device__ __align__(128) __half g_scores[(size_t)N_VECS * N_CODES];
__device__ __align__(128) float g_rowmax[N_VECS];
__device__ __align__(128) float g_enorm[N_CODES];
__device__ __align__(128) int   g_idx[N_VECS];
__device__ __align__(128) float g_enc_sum[N_CODES];
__device__ __align__(128) float g_embed_sum[N_CODES * E_DIM];
__device__ float g_loss;
__device__ float g_n;
__device__ float g_bmax;

// ---------------------------------------------------------------- asm helpers
__device__ __forceinline__ uint32_t smem_u32(const void* p) {
    uint32_t a;
    asm("{ .reg .u64 t; cvta.to.shared.u64 t, %1; cvt.u32.u64 %0, t; }" : "=r"(a) : "l"(p));
    return a;
}
#define CP16(dst, src)   asm volatile("cp.async.cg.shared.global [%0], [%1], 16;" :: "r"(dst), "l"(src) : "memory")
#define CP_COMMIT()      asm volatile("cp.async.commit_group;" ::: "memory")
#define CP_WAIT1()       asm volatile("cp.async.wait_group 1;" ::: "memory")
#define CP_WAIT0()       asm volatile("cp.async.wait_group 0;" ::: "memory")

#define LDSM_X4(r, addr) asm volatile( \
    "ldmatrix.sync.aligned.m8n8.x4.shared.b16 {%0,%1,%2,%3}, [%4];" \
    : "=r"((r)[0]),"=r"((r)[1]),"=r"((r)[2]),"=r"((r)[3]) : "r"(addr))
#define LDSM_X2(r, addr) asm volatile( \
    "ldmatrix.sync.aligned.m8n8.x2.shared.b16 {%0,%1}, [%2];" \
    : "=r"((r)[0]),"=r"((r)[1]) : "r"(addr))

#define MMA16816(c, a, b) asm volatile( \
    "mma.sync.aligned.m16n8k16.row.col.f32.bf16.bf16.f32 " \
    "{%0,%1,%2,%3}, {%4,%5,%6,%7}, {%8,%9}, {%0,%1,%2,%3};" \
    : "+f"((c)[0]),"+f"((c)[1]),"+f"((c)[2]),"+f"((c)[3]) \
    : "r"((a)[0]),"r"((a)[1]),"r"((a)[2]),"r"((a)[3]), "r"((b)[0]),"r"((b)[1]))

// ---------------------------------------------------------------- prep kernels
__global__ void k_zero() {
    int t = blockIdx.x * blockDim.x + threadIdx.x;
    int nt = gridDim.x * blockDim.x;
    for (int i = t; i < N_CODES * E_DIM; i += nt) g_embed_sum[i] = 0.f;
    for (int i = t; i < N_CODES; i += nt) g_enc_sum[i] = 0.f;
    for (int i = t; i < N_VECS; i += nt) g_zn2[i] = 0.f;
    if (t == 0) { g_loss = 0.f; g_bmax = 0.f; }
}

// 0.5*||e||^2, bmax, and bf16 conversion of emb in one pass.
__global__ void k_enorm(const float* __restrict__ emb) {
    int warp = (blockIdx.x * blockDim.x + threadIdx.x) >> 5;
    int lane = threadIdx.x & 31;
    if (warp >= N_CODES) return;
    const float* r = emb + warp * E_DIM;
    float s = 0.f;
    #pragma unroll
    for (int c = 0; c < E_DIM; c += 32) {
        float v = r[c + lane];
        s += v * v;
        g_es0[(size_t)warp * E_DIM + c + lane] = __float2bfloat16(v);
    }
    #pragma unroll
    for (int o = 16; o; o >>= 1) s += __shfl_down_sync(0xffffffffu, s, o);
    if (lane == 0) {
        g_enorm[warp] = 0.5f * s;
        atomicMax((int*)&g_bmax, __float_as_int(sqrtf(s)));   // positive floats
    }
}

// z (b, c, p) -> g_zs0 bf16, g_zfT fp32 [n][k]; accumulate ||z_n||^2
__global__ void k_split_z(const float* __restrict__ z) {
    __shared__ float t[32][33];
    int b  = blockIdx.z;
    int c0 = blockIdx.y * 32;
    int p0 = blockIdx.x * 32;
    #pragma unroll
    for (int i = 0; i < 32; i += 8)
        t[threadIdx.y + i][threadIdx.x] =
            z[((size_t)(b * 256 + c0 + threadIdx.y + i)) * 1024 + p0 + threadIdx.x];
    __syncthreads();
    #pragma unroll
    for (int i = 0; i < 32; i += 8) {
        int n = b * 1024 + p0 + threadIdx.y + i;
        int k = c0 + threadIdx.x;
        float v = t[threadIdx.x][threadIdx.y + i];
        size_t o = (size_t)n * E_DIM + k;
        g_zs0[o] = __float2bfloat16(v);
        g_zfT[o] = v;
        float s = v * v;
        #pragma unroll
        for (int of = 16; of; of >>= 1) s += __shfl_down_sync(0xffffffffu, s, of);
        if (threadIdx.x == 0) atomicAdd(g_zn2 + n, s);
    }
}

// ---------------------------------------------------------------- phase 1: approx GEMM
// 64-row blocks, 2 CTAs/SM. fp16 scores + register per-row max.
__global__ __launch_bounds__(256, 2) void k_mma() {
    extern __shared__ char smem_raw[];
    const uint32_t SB = smem_u32(smem_raw);
    const int tid  = threadIdx.x;
    const int lane = tid & 31;
    const int wid  = tid >> 5;          // warp_n 0..7 (32 codes each)
    const int m0 = blockIdx.x * M_BLK;

    const int a_row = ((lane >> 3) & 1) * 8 + (lane & 7);
    const uint32_t a_res_off = (uint32_t)(a_row * A_STRIDE + ((lane >> 4) & 1) * 16);
    const int lb = lane & 15;
    const uint32_t b_off = (uint32_t)((wid * 32 + (lb & 7)) * 80 + ((lb >> 3) & 1) * 16);

    // tile tt: chunk = tt>>3, kt = tt&7, buf = tt&1
    auto issue_tile = [&](int tt) {
        int kt    = tt & 7;
        int chunk = tt >> 3;
        int buf   = tt & 1;
        #pragma unroll
        for (int i = 0; i < 4; ++i) {
            int li = tid + i * 256;          // 0..1023
            int code = li >> 2, seg = li & 3;
            const char* src = (const char*)(g_es0
                + (size_t)(chunk * N_CHUNK + code) * E_DIM + kt * 32 + seg * 8);
            CP16(SB + SOFF_B + buf * 20480 + code * 80 + seg * 16, src);
        }
        if (kt == 0 && tid < 64) {           // ens for this chunk
            const char* src = (const char*)(g_enorm + chunk * N_CHUNK + tid * 4);
            CP16(SB + SOFF_ENS + (chunk & 1) * 1024 + tid * 16, src);
        }
        CP_COMMIT();
    };

    // A panel (bf16, 64 rows) resident
    #pragma unroll
    for (int i = 0; i < 8; ++i) {
        int li = tid + i * 256;              // 0..2047
        int row = li >> 5, seg = li & 31;
        const char* src = (const char*)(g_zs0 + (size_t)(m0 + row) * E_DIM + seg * 8);
        CP16(SB + SOFF_A + row * A_STRIDE + seg * 16, src);
    }
    CP_COMMIT();
    issue_tile(0);
    issue_tile(1);

    float acc[4][4][4];
    #pragma unroll
    for (int mt = 0; mt < 4; ++mt)
        #pragma unroll
        for (int nt = 0; nt < 4; ++nt)
            #pragma unroll
            for (int j = 0; j < 4; ++j) acc[mt][nt][j] = 0.f;

    float smax[8];
    #pragma unroll
    for (int s = 0; s < 8; ++s) smax[s] = -1e30f;

    for (int tt = 0; tt < N_TILES; ++tt) {
        if (tt == N_TILES - 1) CP_WAIT0(); else CP_WAIT1();
        __syncthreads();

        int kt  = tt & 7;
        int buf = tt & 1;
        uint32_t bbase = SB + SOFF_B + buf * 20480 + b_off;

        #pragma unroll
        for (int km = 0; km < 2; ++km) {
            uint32_t bf[4][2];
            #pragma unroll
            for (int nt = 0; nt < 4; ++nt)
                LDSM_X2(bf[nt], bbase + nt * 640 + km * 32);
            #pragma unroll
            for (int mt = 0; mt < 4; ++mt) {
                uint32_t af[4];
                LDSM_X4(af, SB + SOFF_A + a_res_off
                            + mt * (16 * A_STRIDE) + kt * 64 + km * 32);
                #pragma unroll
                for (int nt = 0; nt < 4; ++nt)
                    MMA16816(acc[mt][nt], af, bf[nt]);
            }
        }
        __syncthreads();
        if (tt + 2 < N_TILES) issue_tile(tt + 2);

        if (kt == 7) {
            // ---- chunk epilogue: subtract enorm, track reg-max, store fp16 ----
            int chunk = tt >> 3;
            const float* ens = (const float*)(smem_raw + SOFF_ENS + (chunk & 1) * 1024);
            #pragma unroll
            for (int mt = 0; mt < 4; ++mt) {
                int row = m0 + mt * 16 + (lane >> 2);
                #pragma unroll
                for (int nt = 0; nt < 4; ++nt) {
                    int cl = wid * 32 + nt * 8 + (lane & 3) * 2;
                    int col = chunk * N_CHUNK + cl;
                    float v0 = acc[mt][nt][0] - ens[cl];
                    float v1 = acc[mt][nt][1] - ens[cl + 1];
                    float v2 = acc[mt][nt][2] - ens[cl];
                    float v3 = acc[mt][nt][3] - ens[cl + 1];
                    smax[mt * 2]     = fmaxf(smax[mt * 2],     fmaxf(v0, v1));
                    smax[mt * 2 + 1] = fmaxf(smax[mt * 2 + 1], fmaxf(v2, v3));
                    *(__half2*)(g_scores + (size_t)row * N_CODES + col) =
                        __floats2half2_rn(v0, v1);
                    *(__half2*)(g_scores + (size_t)(row + 8) * N_CODES + col) =
                        __floats2half2_rn(v2, v3);
                    acc[mt][nt][0] = 0.f; acc[mt][nt][1] = 0.f;
                    acc[mt][nt][2] = 0.f; acc[mt][nt][3] = 0.f;
                }
            }
        }
    }

    // ---- single final per-row max reduction (reuse B smem) ----
    __syncthreads();
    float* redmax = (float*)(smem_raw + SOFF_B);    // 64*32 floats = 8KB
    #pragma unroll
    for (int s = 0; s < 8; ++s) {
        int mt = s >> 1, half = s & 1;
        int row = mt * 16 + half * 8 + (lane >> 2);
        redmax[row * 32 + wid * 4 + (lane & 3)] = smax[s];
    }
    __syncthreads();
    if (tid < M_BLK) {
        float m = redmax[tid * 32];
        #pragma unroll
        for (int t = 1; t < 32; ++t) m = fmaxf(m, redmax[tid * 32 + t]);
        g_rowmax[m0 + tid] = m;
    }
}

// ---------------------------------------------------------------- phase 2: single-pass exact rescore
__global__ __launch_bounds__(256) void k_refine(const float* __restrict__ emb,
                                                float* __restrict__ dout) {
    int w = threadIdx.x >> 5;
    int lane = threadIdx.x & 31;
    int n = blockIdx.x * 8 + w;
    if (n >= N_VECS) return;

    float zr[8];
    #pragma unroll
    for (int j = 0; j < 8; ++j)
        zr[j] = g_zfT[(size_t)n * E_DIM + lane + 32 * j];

    float margin = 0.0158f * sqrtf(g_zn2[n]) * g_bmax + 1.2f;
    float thr = g_rowmax[n] - margin;

    const __half2* sr = (const __half2*)(g_scores + (size_t)n * N_CODES);

    float best_v = -1e30f;
    int   best_i = 0x7fffffff;

    for (int i = 0; i < 64; ++i) {
        float2 v = __half22float2(sr[i * 32 + lane]);
        unsigned mb0 = __ballot_sync(0xffffffffu, v.x >= thr);
        unsigned mb1 = __ballot_sync(0xffffffffu, v.y >= thr);
        unsigned mm = mb0 | mb1;
        while (mm) {
            int l = __ffs(mm) - 1;
            mm &= mm - 1;
            #pragma unroll
            for (int e = 0; e < 2; ++e) {
                if (!((e ? mb1 : mb0) >> l & 1)) continue;
                int c = i * 64 + l * 2 + e;
                const float* er = emb + (size_t)c * E_DIM;
                float d = 0.f;
                #pragma unroll
                for (int j = 0; j < 8; ++j)
                    d = fmaf(zr[j], er[lane + 32 * j], d);
                #pragma unroll
                for (int o = 16; o; o >>= 1) d += __shfl_xor_sync(0xffffffffu, d, o);
                float sv = d - g_enorm[c];
                if (sv > best_v || (sv == best_v && c < best_i)) { best_v = sv; best_i = c; }
            }
        }
    }
    if (lane == 0) {
        g_idx[n] = best_i;
        dout[OFF_IDX + n] = (float)best_i;
    }
}

// ---------------------------------------------------------------- epilogue kernels
__global__ void k_gather(const float* __restrict__ z, const float* __restrict__ emb,
                         float* __restrict__ dout) {
    __shared__ float sred[256];
    int t  = blockIdx.x * blockDim.x + threadIdx.x;
    int nt = gridDim.x * blockDim.x;
    float ls = 0.f;
    for (int e = t; e < TOTAL_ELEMS; e += nt) {
        int p  = e & 1023;
        int c  = (e >> 10) & 255;
        int bb = e >> 18;
        int n  = (bb << 10) + p;
        int code = g_idx[n];
        float zv = z[e];
        float ev = __ldg(emb + (size_t)code * E_DIM + c);
        dout[OFF_ZQ + e] = ev;
        float d = ev - zv;
        ls += d * d;
        atomicAdd(g_embed_sum + (size_t)code * E_DIM + c, zv);
        if (c == 0) atomicAdd(g_enc_sum + code, 1.0f);
    }
    sred[threadIdx.x] = ls;
    __syncthreads();
    for (int s = 128; s; s >>= 1) {
        if (threadIdx.x < s) sred[threadIdx.x] += sred[threadIdx.x + s];
        __syncthreads();
    }
    if (threadIdx.x == 0) atomicAdd(&g_loss, sred[0]);
}

__global__ void k_fin1(const float* __restrict__ cs, float* __restrict__ dout) {
    __shared__ float sn[1024];
    __shared__ float sp[1024];
    int t = threadIdx.x;
    float ln = 0.f, lp = 0.f;
    for (int j = t; j < N_CODES; j += 1024) {
        float es  = g_enc_sum[j];
        float ncs = cs[j] * DECAYF + OMDF * es;
        dout[OFF_CS + j] = ncs;
        ln += ncs;
        float pr = es * (1.0f / (float)N_VECS);
        lp += pr * logf(pr + 1e-10f);
    }
    sn[t] = ln; sp[t] = lp;
    __syncthreads();
    for (int s = 512; s; s >>= 1) {
        if (t < s) { sn[t] += sn[t + s]; sp[t] += sp[t + s]; }
        __syncthreads();
    }
    if (t == 0) {
        g_n = sn[0];
        dout[OFF_PERP] = expf(-sp[0]);
        dout[OFF_LOSS] = g_loss * (BETAF / (float)TOTAL_ELEMS);
    }
}

__global__ void k_fin2(const float* __restrict__ ea, float* __restrict__ dout) {
    int i = blockIdx.x * blockDim.x + threadIdx.x;
    if (i >= N_CODES * E_DIM) return;
    int code = i >> 8;
    float nea = ea[i] * DECAYF + OMDF * g_embed_sum[i];
    dout[OFF_EA + i] = nea;
    float ncs = dout[OFF_CS + code];
    float n = g_n;
    float sm = (ncs + EPSF) / (n + (float)N_CODES * EPSF) * n;
    dout[OFF_EMB + i] = nea / sm;
}

// ---------------------------------------------------------------- launch
extern "C" void kernel_launch(void* const* d_in, const int* in_sizes, int n_in,
                              void* d_out, int out_size) {
    const float* z   = (const float*)d_in[0];
    const float* emb = (const float*)d_in[1];
    const float* cs  = (const float*)d_in[2];
    const float* ea  = (const float*)d_in[3];
    float* out = (float*)d_out;

    cudaFuncSetAttribute(k_mma, cudaFuncAttributeMaxDynamicSharedMemorySize, SMEM_TOTAL);

    k_zero<<<1024, 512>>>();
    k_enorm<<<512, 256>>>(emb);
    k_split_z<<<dim3(32, 8, 16), dim3(32, 8)>>>(z);
    k_mma<<<N_VECS / M_BLK, 256, SMEM_TOTAL>>>();
    k_refine<<<N_VECS / 8, 256>>>(emb, out);
    k_gather<<<4096, 256>>>(z, emb, out);
    k_fin1<<<1, 1024>>>(cs, out);
    k_fin2<<<4096, 256>>>(ea, out);
}

// round 13
// speedup vs baseline: 1.1082x; 1.0351x over previous
#include <cuda_runtime.h>
#include <cuda_bf16.h>
#include <cuda_fp16.h>
#include <math.h>
#include <stdint.h>

// ---------------------------------------------------------------- constants
#define TOTAL_ELEMS (16*256*1024)
#define N_CODES 4096
#define E_DIM   256
#define N_VECS  16384
#define DECAYF  0.99f
#define OMDF    0.01f
#define BETAF   0.25f
#define EPSF    1e-5f

#define OFF_LOSS 0
#define OFF_ZQ   1
#define OFF_PERP (1 + TOTAL_ELEMS)
#define OFF_IDX  (2 + TOTAL_ELEMS)
#define OFF_EMB  (2 + TOTAL_ELEMS + N_VECS)
#define OFF_CS   (OFF_EMB + N_CODES*E_DIM)
#define OFF_EA   (OFF_CS + N_CODES)

// Phase-1 GEMM: block = 64 rows x 256-code chunks (16 chunks), bf16 a0*b0.
// 8 warps, warp tile 64x32 (warp_n = wid). 2 CTAs/SM. 3-stage cp.async ring,
// ONE __syncthreads per tile, issue-ahead before compute.
#define M_BLK 64
#define N_CHUNK 256
#define N_CHUNKS 16
#define N_TILES (N_CHUNKS * 8)      // 8 k-tiles of 32 per chunk

// smem layout (bytes from base)
#define A_STRIDE 528                // 256 bf16 = 512B + 16 pad (ldmatrix conflict-free)
#define SOFF_A    0                 // 64 x 528 = 33792
#define SOFF_B    33792             // 3 bufs x 256*80 = 61440 (reused for final reduce)
#define SOFF_ENS  95232             // 2 bufs x 1024
#define SMEM_TOTAL 97280            // x2 CTAs = 190.5KB <= 228KB/SM

// ---------------------------------------------------------------- scratch
__device__ __align__(128) __nv_bfloat16 g_zs0[(size_t)N_VECS * E_DIM];
__device__ __align__(128) __nv_bfloat16 g_es0[(size_t)N_CODES * E_DIM];
__device__ __align__(128) float g_zfT[(size_t)N_VECS * E_DIM];   // fp32, n-major
__device__ __align__(128) float g_zn2[N_VECS];                   // ||z_n||^2
__device__ __align__(128) __half g_scores[(size_t)N_VECS * N_CODES];
__device__ __align__(128) float g_rowmax[N_VECS];
__device__ __align__(128) float g_enorm[N_CODES];
__device__ __align__(128) int   g_idx[N_VECS];
__device__ __align__(128) float g_enc_sum[N_CODES];
__device__ __align__(128) float g_embed_sum[N_CODES * E_DIM];
__device__ float g_loss;
__device__ float g_n;
__device__ float g_bmax;

// ---------------------------------------------------------------- asm helpers
__device__ __forceinline__ uint32_t smem_u32(const void* p) {
    uint32_t a;
    asm("{ .reg .u64 t; cvta.to.shared.u64 t, %1; cvt.u32.u64 %0, t; }" : "=r"(a) : "l"(p));
    return a;
}
#define CP16(dst, src)   asm volatile("cp.async.cg.shared.global [%0], [%1], 16;" :: "r"(dst), "l"(src) : "memory")
#define CP_COMMIT()      asm volatile("cp.async.commit_group;" ::: "memory")
#define CP_WAIT1()       asm volatile("cp.async.wait_group 1;" ::: "memory")
#define CP_WAIT0()       asm volatile("cp.async.wait_group 0;" ::: "memory")

#define LDSM_X4(r, addr) asm volatile( \
    "ldmatrix.sync.aligned.m8n8.x4.shared.b16 {%0,%1,%2,%3}, [%4];" \
    : "=r"((r)[0]),"=r"((r)[1]),"=r"((r)[2]),"=r"((r)[3]) : "r"(addr))

#define MMA16816(c, a, b) asm volatile( \
    "mma.sync.aligned.m16n8k16.row.col.f32.bf16.bf16.f32 " \
    "{%0,%1,%2,%3}, {%4,%5,%6,%7}, {%8,%9}, {%0,%1,%2,%3};" \
    : "+f"((c)[0]),"+f"((c)[1]),"+f"((c)[2]),"+f"((c)[3]) \
    : "r"((a)[0]),"r"((a)[1]),"r"((a)[2]),"r"((a)[3]), "r"((b)[0]),"r"((b)[1]))

// ---------------------------------------------------------------- prep kernels
__global__ void k_zero() {
    int t = blockIdx.x * blockDim.x + threadIdx.x;
    int nt = gridDim.x * blockDim.x;
    for (int i = t; i < N_CODES * E_DIM; i += nt) g_embed_sum[i] = 0.f;
    for (int i = t; i < N_CODES; i += nt) g_enc_sum[i] = 0.f;
    for (int i = t; i < N_VECS; i += nt) g_zn2[i] = 0.f;
    if (t == 0) { g_loss = 0.f; g_bmax = 0.f; }
}

// 0.5*||e||^2, bmax, and bf16 conversion of emb in one pass.
__global__ void k_enorm(const float* __restrict__ emb) {
    int warp = (blockIdx.x * blockDim.x + threadIdx.x) >> 5;
    int lane = threadIdx.x & 31;
    if (warp >= N_CODES) return;
    const float* r = emb + warp * E_DIM;
    float s = 0.f;
    #pragma unroll
    for (int c = 0; c < E_DIM; c += 32) {
        float v = r[c + lane];
        s += v * v;
        g_es0[(size_t)warp * E_DIM + c + lane] = __float2bfloat16(v);
    }
    #pragma unroll
    for (int o = 16; o; o >>= 1) s += __shfl_down_sync(0xffffffffu, s, o);
    if (lane == 0) {
        g_enorm[warp] = 0.5f * s;
        atomicMax((int*)&g_bmax, __float_as_int(sqrtf(s)));   // positive floats
    }
}

// z (b, c, p) -> g_zs0 bf16, g_zfT fp32 [n][k]; accumulate ||z_n||^2
__global__ void k_split_z(const float* __restrict__ z) {
    __shared__ float t[32][33];
    int b  = blockIdx.z;
    int c0 = blockIdx.y * 32;
    int p0 = blockIdx.x * 32;
    #pragma unroll
    for (int i = 0; i < 32; i += 8)
        t[threadIdx.y + i][threadIdx.x] =
            z[((size_t)(b * 256 + c0 + threadIdx.y + i)) * 1024 + p0 + threadIdx.x];
    __syncthreads();
    #pragma unroll
    for (int i = 0; i < 32; i += 8) {
        int n = b * 1024 + p0 + threadIdx.y + i;
        int k = c0 + threadIdx.x;
        float v = t[threadIdx.x][threadIdx.y + i];
        size_t o = (size_t)n * E_DIM + k;
        g_zs0[o] = __float2bfloat16(v);
        g_zfT[o] = v;
        float s = v * v;
        #pragma unroll
        for (int of = 16; of; of >>= 1) s += __shfl_down_sync(0xffffffffu, s, of);
        if (threadIdx.x == 0) atomicAdd(g_zn2 + n, s);
    }
}

// ---------------------------------------------------------------- phase 1: approx GEMM
// 3-stage pipeline, one sync/tile, B fragments via LDSM_X4 pairs.
__global__ __launch_bounds__(256, 2) void k_mma() {
    extern __shared__ char smem_raw[];
    const uint32_t SB = smem_u32(smem_raw);
    const int tid  = threadIdx.x;
    const int lane = tid & 31;
    const int wid  = tid >> 5;          // warp_n 0..7 (32 codes each)
    const int m0 = blockIdx.x * M_BLK;

    const int a_row = ((lane >> 3) & 1) * 8 + (lane & 7);
    const uint32_t a_res_off = (uint32_t)(a_row * A_STRIDE + ((lane >> 4) & 1) * 16);
    // X4 B address: lanes 0-15 -> n-rows base..base+7 (k-halves), lanes 16-31 -> base+8..15
    const uint32_t b_off4 = (uint32_t)((wid * 32 + ((lane >> 4) & 1) * 8 + (lane & 7)) * 80
                                       + ((lane >> 3) & 1) * 16);

    // tile tt: chunk = tt>>3, kt = tt&7, buf = tt%3
    auto issue_tile = [&](int tt) {
        int kt    = tt & 7;
        int chunk = tt >> 3;
        int buf   = tt % 3;
        #pragma unroll
        for (int i = 0; i < 4; ++i) {
            int li = tid + i * 256;          // 0..1023
            int code = li >> 2, seg = li & 3;
            const char* src = (const char*)(g_es0
                + (size_t)(chunk * N_CHUNK + code) * E_DIM + kt * 32 + seg * 8);
            CP16(SB + SOFF_B + buf * 20480 + code * 80 + seg * 16, src);
        }
        if (kt == 0 && tid < 64) {           // ens for this chunk
            const char* src = (const char*)(g_enorm + chunk * N_CHUNK + tid * 4);
            CP16(SB + SOFF_ENS + (chunk & 1) * 1024 + tid * 16, src);
        }
        CP_COMMIT();
    };

    // A panel (bf16, 64 rows) resident
    #pragma unroll
    for (int i = 0; i < 8; ++i) {
        int li = tid + i * 256;              // 0..2047
        int row = li >> 5, seg = li & 31;
        const char* src = (const char*)(g_zs0 + (size_t)(m0 + row) * E_DIM + seg * 8);
        CP16(SB + SOFF_A + row * A_STRIDE + seg * 16, src);
    }
    CP_COMMIT();
    issue_tile(0);
    issue_tile(1);

    float acc[4][4][4];
    #pragma unroll
    for (int mt = 0; mt < 4; ++mt)
        #pragma unroll
        for (int nt = 0; nt < 4; ++nt)
            #pragma unroll
            for (int j = 0; j < 4; ++j) acc[mt][nt][j] = 0.f;

    float smax[8];
    #pragma unroll
    for (int s = 0; s < 8; ++s) smax[s] = -1e30f;

    for (int tt = 0; tt < N_TILES; ++tt) {
        // tile tt data ready (groups newer than tt: only tt+1 outstanding here)
        if (tt == N_TILES - 1) CP_WAIT0(); else CP_WAIT1();
        __syncthreads();    // publishes buf tt; proves all warps done with tt-1
        if (tt + 2 < N_TILES) issue_tile(tt + 2);   // overwrite buf (tt+2)%3 == (tt-1)%3: safe

        int kt  = tt & 7;
        int buf = tt % 3;
        uint32_t bbase4 = SB + SOFF_B + buf * 20480 + b_off4;

        #pragma unroll
        for (int km = 0; km < 2; ++km) {
            uint32_t bf[4][2];
            #pragma unroll
            for (int p = 0; p < 2; ++p) {
                uint32_t r[4];
                LDSM_X4(r, bbase4 + p * 1280 + km * 32);   // 16 n-rows x 2 k-halves
                bf[2*p][0] = r[0]; bf[2*p][1] = r[1];
                bf[2*p+1][0] = r[2]; bf[2*p+1][1] = r[3];
            }
            #pragma unroll
            for (int mt = 0; mt < 4; ++mt) {
                uint32_t af[4];
                LDSM_X4(af, SB + SOFF_A + a_res_off
                            + mt * (16 * A_STRIDE) + kt * 64 + km * 32);
                #pragma unroll
                for (int nt = 0; nt < 4; ++nt)
                    MMA16816(acc[mt][nt], af, bf[nt]);
            }
        }

        if (kt == 7) {
            // ---- chunk epilogue: subtract enorm, track reg-max, store fp16 ----
            int chunk = tt >> 3;
            const float* ens = (const float*)(smem_raw + SOFF_ENS + (chunk & 1) * 1024);
            #pragma unroll
            for (int mt = 0; mt < 4; ++mt) {
                int row = m0 + mt * 16 + (lane >> 2);
                #pragma unroll
                for (int nt = 0; nt < 4; ++nt) {
                    int cl = wid * 32 + nt * 8 + (lane & 3) * 2;
                    int col = chunk * N_CHUNK + cl;
                    float v0 = acc[mt][nt][0] - ens[cl];
                    float v1 = acc[mt][nt][1] - ens[cl + 1];
                    float v2 = acc[mt][nt][2] - ens[cl];
                    float v3 = acc[mt][nt][3] - ens[cl + 1];
                    smax[mt * 2]     = fmaxf(smax[mt * 2],     fmaxf(v0, v1));
                    smax[mt * 2 + 1] = fmaxf(smax[mt * 2 + 1], fmaxf(v2, v3));
                    *(__half2*)(g_scores + (size_t)row * N_CODES + col) =
                        __floats2half2_rn(v0, v1);
                    *(__half2*)(g_scores + (size_t)(row + 8) * N_CODES + col) =
                        __floats2half2_rn(v2, v3);
                    acc[mt][nt][0] = 0.f; acc[mt][nt][1] = 0.f;
                    acc[mt][nt][2] = 0.f; acc[mt][nt][3] = 0.f;
                }
            }
        }
    }

    // ---- single final per-row max reduction (reuse B smem) ----
    __syncthreads();
    float* redmax = (float*)(smem_raw + SOFF_B);    // 64*32 floats = 8KB
    #pragma unroll
    for (int s = 0; s < 8; ++s) {
        int mt = s >> 1, half = s & 1;
        int row = mt * 16 + half * 8 + (lane >> 2);
        redmax[row * 32 + wid * 4 + (lane & 3)] = smax[s];
    }
    __syncthreads();
    if (tid < M_BLK) {
        float m = redmax[tid * 32];
        #pragma unroll
        for (int t = 1; t < 32; ++t) m = fmaxf(m, redmax[tid * 32 + t]);
        g_rowmax[m0 + tid] = m;
    }
}

// ---------------------------------------------------------------- phase 2: single-pass exact rescore
__global__ __launch_bounds__(256) void k_refine(const float* __restrict__ emb,
                                                float* __restrict__ dout) {
    int w = threadIdx.x >> 5;
    int lane = threadIdx.x & 31;
    int n = blockIdx.x * 8 + w;
    if (n >= N_VECS) return;

    float zr[8];
    #pragma unroll
    for (int j = 0; j < 8; ++j)
        zr[j] = g_zfT[(size_t)n * E_DIM + lane + 32 * j];

    float margin = 0.0158f * sqrtf(g_zn2[n]) * g_bmax + 1.2f;
    float thr = g_rowmax[n] - margin;

    const __half2* sr = (const __half2*)(g_scores + (size_t)n * N_CODES);

    float best_v = -1e30f;
    int   best_i = 0x7fffffff;

    for (int i = 0; i < 64; ++i) {
        float2 v = __half22float2(sr[i * 32 + lane]);
        unsigned mb0 = __ballot_sync(0xffffffffu, v.x >= thr);
        unsigned mb1 = __ballot_sync(0xffffffffu, v.y >= thr);
        unsigned mm = mb0 | mb1;
        while (mm) {
            int l = __ffs(mm) - 1;
            mm &= mm - 1;
            #pragma unroll
            for (int e = 0; e < 2; ++e) {
                if (!((e ? mb1 : mb0) >> l & 1)) continue;
                int c = i * 64 + l * 2 + e;
                const float* er = emb + (size_t)c * E_DIM;
                float d = 0.f;
                #pragma unroll
                for (int j = 0; j < 8; ++j)
                    d = fmaf(zr[j], er[lane + 32 * j], d);
                #pragma unroll
                for (int o = 16; o; o >>= 1) d += __shfl_xor_sync(0xffffffffu, d, o);
                float sv = d - g_enorm[c];
                if (sv > best_v || (sv == best_v && c < best_i)) { best_v = sv; best_i = c; }
            }
        }
    }
    if (lane == 0) {
        g_idx[n] = best_i;
        dout[OFF_IDX + n] = (float)best_i;
    }
}

// ---------------------------------------------------------------- epilogue kernels
__global__ void k_gather(const float* __restrict__ z, const float* __restrict__ emb,
                         float* __restrict__ dout) {
    __shared__ float sred[256];
    int t  = blockIdx.x * blockDim.x + threadIdx.x;
    int nt = gridDim.x * blockDim.x;
    float ls = 0.f;
    for (int e = t; e < TOTAL_ELEMS; e += nt) {
        int p  = e & 1023;
        int c  = (e >> 10) & 255;
        int bb = e >> 18;
        int n  = (bb << 10) + p;
        int code = g_idx[n];
        float zv = z[e];
        float ev = __ldg(emb + (size_t)code * E_DIM + c);
        dout[OFF_ZQ + e] = ev;
        float d = ev - zv;
        ls += d * d;
        atomicAdd(g_embed_sum + (size_t)code * E_DIM + c, zv);
        if (c == 0) atomicAdd(g_enc_sum + code, 1.0f);
    }
    sred[threadIdx.x] = ls;
    __syncthreads();
    for (int s = 128; s; s >>= 1) {
        if (threadIdx.x < s) sred[threadIdx.x] += sred[threadIdx.x + s];
        __syncthreads();
    }
    if (threadIdx.x == 0) atomicAdd(&g_loss, sred[0]);
}

__global__ void k_fin1(const float* __restrict__ cs, float* __restrict__ dout) {
    __shared__ float sn[1024];
    __shared__ float sp[1024];
    int t = threadIdx.x;
    float ln = 0.f, lp = 0.f;
    for (int j = t; j < N_CODES; j += 1024) {
        float es  = g_enc_sum[j];
        float ncs = cs[j] * DECAYF + OMDF * es;
        dout[OFF_CS + j] = ncs;
        ln += ncs;
        float pr = es * (1.0f / (float)N_VECS);
        lp += pr * logf(pr + 1e-10f);
    }
    sn[t] = ln; sp[t] = lp;
    __syncthreads();
    for (int s = 512; s; s >>= 1) {
        if (t < s) { sn[t] += sn[t + s]; sp[t] += sp[t + s]; }
        __syncthreads();
    }
    if (t == 0) {
        g_n = sn[0];
        dout[OFF_PERP] = expf(-sp[0]);
        dout[OFF_LOSS] = g_loss * (BETAF / (float)TOTAL_ELEMS);
    }
}

__global__ void k_fin2(const float* __restrict__ ea, float* __restrict__ dout) {
    int i = blockIdx.x * blockDim.x + threadIdx.x;
    if (i >= N_CODES * E_DIM) return;
    int code = i >> 8;
    float nea = ea[i] * DECAYF + OMDF * g_embed_sum[i];
    dout[OFF_EA + i] = nea;
    float ncs = dout[OFF_CS + code];
    float n = g_n;
    float sm = (ncs + EPSF) / (n + (float)N_CODES * EPSF) * n;
    dout[OFF_EMB + i] = nea / sm;
}

// ---------------------------------------------------------------- launch
extern "C" void kernel_launch(void* const* d_in, const int* in_sizes, int n_in,
                              void* d_out, int out_size) {
    const float* z   = (const float*)d_in[0];
    const float* emb = (const float*)d_in[1];
    const float* cs  = (const float*)d_in[2];
    const float* ea  = (const float*)d_in[3];
    float* out = (float*)d_out;

    cudaFuncSetAttribute(k_mma, cudaFuncAttributeMaxDynamicSharedMemorySize, SMEM_TOTAL);

    k_zero<<<1024, 512>>>();
    k_enorm<<<512, 256>>>(emb);
    k_split_z<<<dim3(32, 8, 16), dim3(32, 8)>>>(z);
    k_mma<<<N_VECS / M_BLK, 256, SMEM_TOTAL>>>();
    k_refine<<<N_VECS / 8, 256>>>(emb, out);
    k_gather<<<4096, 256>>>(z, emb, out);
    k_fin1<<<1, 1024>>>(cs, out);
    k_fin2<<<4096, 256>>>(ea, out);
}

// round 14
// speedup vs baseline: 1.2179x; 1.0991x over previous
#include <cuda_runtime.h>
#include <cuda_bf16.h>
#include <cuda_fp16.h>
#include <math.h>
#include <stdint.h>

// ---------------------------------------------------------------- constants
#define TOTAL_ELEMS (16*256*1024)
#define N_CODES 4096
#define E_DIM   256
#define N_VECS  16384
#define DECAYF  0.99f
#define OMDF    0.01f
#define BETAF   0.25f
#define EPSF    1e-5f

#define OFF_LOSS 0
#define OFF_ZQ   1
#define OFF_PERP (1 + TOTAL_ELEMS)
#define OFF_IDX  (2 + TOTAL_ELEMS)
#define OFF_EMB  (2 + TOTAL_ELEMS + N_VECS)
#define OFF_CS   (OFF_EMB + N_CODES*E_DIM)
#define OFF_EA   (OFF_CS + N_CODES)

// Phase-1 GEMM: block = 64 rows x 256-code chunks (16 chunks), bf16 a0*b0.
// 8 warps, warp tile 64x32. B slices are WARP-PRIVATE: per-warp cp.async ring,
// per-warp wait_group, ZERO block barriers in the 128-tile main loop.
#define M_BLK 64
#define N_CHUNK 256
#define N_CHUNKS 16
#define N_TILES (N_CHUNKS * 8)      // 8 k-tiles of 32 per chunk

// smem layout (bytes from base)
#define A_STRIDE 528                // 256 bf16 = 512B + 16 pad (ldmatrix conflict-free)
#define SOFF_A    0                 // 64 x 528 = 33792
#define SOFF_B    33792             // 3 bufs x 8 warps x 2560 = 61440 (reused for reduce)
#define SMEM_TOTAL 95232            // x2 CTAs = 190.5KB <= 228KB/SM

// ---------------------------------------------------------------- scratch
__device__ __align__(128) __nv_bfloat16 g_zs0[(size_t)N_VECS * E_DIM];
__device__ __align__(128) __nv_bfloat16 g_es0[(size_t)N_CODES * E_DIM];
__device__ __align__(128) float g_zfT[(size_t)N_VECS * E_DIM];   // fp32, n-major
__device__ __align__(128) float g_zn2[N_VECS];                   // ||z_n||^2
__device__ __align__(128) __half g_scores[(size_t)N_VECS * N_CODES];
__device__ __align__(128) float g_rowmax[N_VECS];
__device__ __align__(128) float g_enorm[N_CODES];
__device__ __align__(128) int   g_idx[N_VECS];
__device__ __align__(128) float g_enc_sum[N_CODES];
__device__ __align__(128) float g_embed_sum[N_CODES * E_DIM];
__device__ float g_loss;
__device__ float g_n;
__device__ float g_bmax;

// ---------------------------------------------------------------- asm helpers
__device__ __forceinline__ uint32_t smem_u32(const void* p) {
    uint32_t a;
    asm("{ .reg .u64 t; cvta.to.shared.u64 t, %1; cvt.u32.u64 %0, t; }" : "=r"(a) : "l"(p));
    return a;
}
#define CP16(dst, src)   asm volatile("cp.async.cg.shared.global [%0], [%1], 16;" :: "r"(dst), "l"(src) : "memory")
#define CP_COMMIT()      asm volatile("cp.async.commit_group;" ::: "memory")
#define CP_WAIT1()       asm volatile("cp.async.wait_group 1;" ::: "memory")
#define CP_WAIT0()       asm volatile("cp.async.wait_group 0;" ::: "memory")

#define LDSM_X4(r, addr) asm volatile( \
    "ldmatrix.sync.aligned.m8n8.x4.shared.b16 {%0,%1,%2,%3}, [%4];" \
    : "=r"((r)[0]),"=r"((r)[1]),"=r"((r)[2]),"=r"((r)[3]) : "r"(addr))

#define MMA16816(c, a, b) asm volatile( \
    "mma.sync.aligned.m16n8k16.row.col.f32.bf16.bf16.f32 " \
    "{%0,%1,%2,%3}, {%4,%5,%6,%7}, {%8,%9}, {%0,%1,%2,%3};" \
    : "+f"((c)[0]),"+f"((c)[1]),"+f"((c)[2]),"+f"((c)[3]) \
    : "r"((a)[0]),"r"((a)[1]),"r"((a)[2]),"r"((a)[3]), "r"((b)[0]),"r"((b)[1]))

// ---------------------------------------------------------------- prep kernels
__global__ void k_zero() {
    int t = blockIdx.x * blockDim.x + threadIdx.x;
    int nt = gridDim.x * blockDim.x;
    for (int i = t; i < N_CODES * E_DIM; i += nt) g_embed_sum[i] = 0.f;
    for (int i = t; i < N_CODES; i += nt) g_enc_sum[i] = 0.f;
    for (int i = t; i < N_VECS; i += nt) g_zn2[i] = 0.f;
    if (t == 0) { g_loss = 0.f; g_bmax = 0.f; }
}

// 0.5*||e||^2, bmax, and bf16 conversion of emb in one pass.
__global__ void k_enorm(const float* __restrict__ emb) {
    int warp = (blockIdx.x * blockDim.x + threadIdx.x) >> 5;
    int lane = threadIdx.x & 31;
    if (warp >= N_CODES) return;
    const float* r = emb + warp * E_DIM;
    float s = 0.f;
    #pragma unroll
    for (int c = 0; c < E_DIM; c += 32) {
        float v = r[c + lane];
        s += v * v;
        g_es0[(size_t)warp * E_DIM + c + lane] = __float2bfloat16(v);
    }
    #pragma unroll
    for (int o = 16; o; o >>= 1) s += __shfl_down_sync(0xffffffffu, s, o);
    if (lane == 0) {
        g_enorm[warp] = 0.5f * s;
        atomicMax((int*)&g_bmax, __float_as_int(sqrtf(s)));   // positive floats
    }
}

// z (b, c, p) -> g_zs0 bf16, g_zfT fp32 [n][k]; accumulate ||z_n||^2
__global__ void k_split_z(const float* __restrict__ z) {
    __shared__ float t[32][33];
    int b  = blockIdx.z;
    int c0 = blockIdx.y * 32;
    int p0 = blockIdx.x * 32;
    #pragma unroll
    for (int i = 0; i < 32; i += 8)
        t[threadIdx.y + i][threadIdx.x] =
            z[((size_t)(b * 256 + c0 + threadIdx.y + i)) * 1024 + p0 + threadIdx.x];
    __syncthreads();
    #pragma unroll
    for (int i = 0; i < 32; i += 8) {
        int n = b * 1024 + p0 + threadIdx.y + i;
        int k = c0 + threadIdx.x;
        float v = t[threadIdx.x][threadIdx.y + i];
        size_t o = (size_t)n * E_DIM + k;
        g_zs0[o] = __float2bfloat16(v);
        g_zfT[o] = v;
        float s = v * v;
        #pragma unroll
        for (int of = 16; of; of >>= 1) s += __shfl_down_sync(0xffffffffu, s, of);
        if (threadIdx.x == 0) atomicAdd(g_zn2 + n, s);
    }
}

// ---------------------------------------------------------------- phase 1: approx GEMM
// Warp-private B pipeline: no block barriers in the main loop.
__global__ __launch_bounds__(256, 2) void k_mma() {
    extern __shared__ char smem_raw[];
    const uint32_t SB = smem_u32(smem_raw);
    const int tid  = threadIdx.x;
    const int lane = tid & 31;
    const int wid  = tid >> 5;          // warp_n 0..7 (32 codes each)
    const int m0 = blockIdx.x * M_BLK;

    const int a_row = ((lane >> 3) & 1) * 8 + (lane & 7);
    const uint32_t a_res_off = (uint32_t)(a_row * A_STRIDE + ((lane >> 4) & 1) * 16);
    // X4 B address within warp slice: row = (lane>>4&1)*8 + (lane&7), k-half = (lane>>3)&1
    const uint32_t b_loc4 = (uint32_t)((((lane >> 4) & 1) * 8 + (lane & 7)) * 80
                                       + ((lane >> 3) & 1) * 16);

    // per-warp B slice issue: 32 codes x 64B data (80B stride), 4 CP16/lane
    auto issue_tile = [&](int tt) {
        int kt    = tt & 7;
        int chunk = tt >> 3;
        uint32_t wB = SB + SOFF_B + (tt % 3) * 20480 + wid * 2560;
        #pragma unroll
        for (int i = 0; i < 4; ++i) {
            int j = lane + i * 32;           // 0..127
            int code = j >> 2, seg = j & 3;
            const char* src = (const char*)(g_es0
                + (size_t)(chunk * N_CHUNK + wid * 32 + code) * E_DIM + kt * 32 + seg * 8);
            CP16(wB + code * 80 + seg * 16, src);
        }
        CP_COMMIT();
    };

    // A panel (bf16, 64 rows) cooperative load (group 0 per warp)
    #pragma unroll
    for (int i = 0; i < 8; ++i) {
        int li = tid + i * 256;              // 0..2047
        int row = li >> 5, seg = li & 31;
        const char* src = (const char*)(g_zs0 + (size_t)(m0 + row) * E_DIM + seg * 8);
        CP16(SB + SOFF_A + row * A_STRIDE + seg * 16, src);
    }
    CP_COMMIT();
    issue_tile(0);
    issue_tile(1);

    float acc[4][4][4];
    #pragma unroll
    for (int mt = 0; mt < 4; ++mt)
        #pragma unroll
        for (int nt = 0; nt < 4; ++nt)
            #pragma unroll
            for (int j = 0; j < 4; ++j) acc[mt][nt][j] = 0.f;

    float smax[8];
    #pragma unroll
    for (int s = 0; s < 8; ++s) smax[s] = -1e30f;

    float ens_v = 0.f;                       // this warp's 32 enorm values (by lane)

    for (int tt = 0; tt < N_TILES; ++tt) {
        // own-stream wait: tile tt's B slice (and A at tt=0) complete
        if (tt == N_TILES - 1) CP_WAIT0(); else CP_WAIT1();
        if (tt == 0) __syncthreads();        // publish A across warps (only block barrier)
        if (tt + 2 < N_TILES) issue_tile(tt + 2);   // own ring: buf (tt+2)%3 == (tt-1)%3, done

        int kt = tt & 7;
        if (kt == 0)                         // prefetch enorm for this chunk (used at kt==7)
            ens_v = __ldg(g_enorm + (tt >> 3) * N_CHUNK + wid * 32 + lane);

        uint32_t bbase4 = SB + SOFF_B + (tt % 3) * 20480 + wid * 2560 + b_loc4;

        #pragma unroll
        for (int km = 0; km < 2; ++km) {
            uint32_t bf[4][2];
            #pragma unroll
            for (int p = 0; p < 2; ++p) {
                uint32_t r[4];
                LDSM_X4(r, bbase4 + p * 1280 + km * 32);   // 16 n-rows x 2 k-halves
                bf[2*p][0] = r[0]; bf[2*p][1] = r[1];
                bf[2*p+1][0] = r[2]; bf[2*p+1][1] = r[3];
            }
            #pragma unroll
            for (int mt = 0; mt < 4; ++mt) {
                uint32_t af[4];
                LDSM_X4(af, SB + SOFF_A + a_res_off
                            + mt * (16 * A_STRIDE) + kt * 64 + km * 32);
                #pragma unroll
                for (int nt = 0; nt < 4; ++nt)
                    MMA16816(acc[mt][nt], af, bf[nt]);
            }
        }

        if (kt == 7) {
            // ---- chunk epilogue: enorm via shuffle, reg-max, fp16 store ----
            int chunk = tt >> 3;
            float ensl[4][2];
            #pragma unroll
            for (int nt = 0; nt < 4; ++nt) {
                int li = nt * 8 + (lane & 3) * 2;
                ensl[nt][0] = __shfl_sync(0xffffffffu, ens_v, li);
                ensl[nt][1] = __shfl_sync(0xffffffffu, ens_v, li + 1);
            }
            #pragma unroll
            for (int mt = 0; mt < 4; ++mt) {
                int row = m0 + mt * 16 + (lane >> 2);
                #pragma unroll
                for (int nt = 0; nt < 4; ++nt) {
                    int col = chunk * N_CHUNK + wid * 32 + nt * 8 + (lane & 3) * 2;
                    float v0 = acc[mt][nt][0] - ensl[nt][0];
                    float v1 = acc[mt][nt][1] - ensl[nt][1];
                    float v2 = acc[mt][nt][2] - ensl[nt][0];
                    float v3 = acc[mt][nt][3] - ensl[nt][1];
                    smax[mt * 2]     = fmaxf(smax[mt * 2],     fmaxf(v0, v1));
                    smax[mt * 2 + 1] = fmaxf(smax[mt * 2 + 1], fmaxf(v2, v3));
                    *(__half2*)(g_scores + (size_t)row * N_CODES + col) =
                        __floats2half2_rn(v0, v1);
                    *(__half2*)(g_scores + (size_t)(row + 8) * N_CODES + col) =
                        __floats2half2_rn(v2, v3);
                    acc[mt][nt][0] = 0.f; acc[mt][nt][1] = 0.f;
                    acc[mt][nt][2] = 0.f; acc[mt][nt][3] = 0.f;
                }
            }
        }
    }

    // ---- single final per-row max reduction (reuse B smem) ----
    __syncthreads();
    float* redmax = (float*)(smem_raw + SOFF_B);    // 64*32 floats = 8KB
    #pragma unroll
    for (int s = 0; s < 8; ++s) {
        int mt = s >> 1, half = s & 1;
        int row = mt * 16 + half * 8 + (lane >> 2);
        redmax[row * 32 + wid * 4 + (lane & 3)] = smax[s];
    }
    __syncthreads();
    if (tid < M_BLK) {
        float m = redmax[tid * 32];
        #pragma unroll
        for (int t = 1; t < 32; ++t) m = fmaxf(m, redmax[tid * 32 + t]);
        g_rowmax[m0 + tid] = m;
    }
}

// ---------------------------------------------------------------- phase 2: single-pass exact rescore
__global__ __launch_bounds__(256) void k_refine(const float* __restrict__ emb,
                                                float* __restrict__ dout) {
    int w = threadIdx.x >> 5;
    int lane = threadIdx.x & 31;
    int n = blockIdx.x * 8 + w;
    if (n >= N_VECS) return;

    float zr[8];
    #pragma unroll
    for (int j = 0; j < 8; ++j)
        zr[j] = g_zfT[(size_t)n * E_DIM + lane + 32 * j];

    float margin = 0.0158f * sqrtf(g_zn2[n]) * g_bmax + 1.2f;
    float thr = g_rowmax[n] - margin;

    const __half2* sr = (const __half2*)(g_scores + (size_t)n * N_CODES);

    float best_v = -1e30f;
    int   best_i = 0x7fffffff;

    for (int i = 0; i < 64; ++i) {
        float2 v = __half22float2(sr[i * 32 + lane]);
        unsigned mb0 = __ballot_sync(0xffffffffu, v.x >= thr);
        unsigned mb1 = __ballot_sync(0xffffffffu, v.y >= thr);
        unsigned mm = mb0 | mb1;
        while (mm) {
            int l = __ffs(mm) - 1;
            mm &= mm - 1;
            #pragma unroll
            for (int e = 0; e < 2; ++e) {
                if (!((e ? mb1 : mb0) >> l & 1)) continue;
                int c = i * 64 + l * 2 + e;
                const float* er = emb + (size_t)c * E_DIM;
                float d = 0.f;
                #pragma unroll
                for (int j = 0; j < 8; ++j)
                    d = fmaf(zr[j], er[lane + 32 * j], d);
                #pragma unroll
                for (int o = 16; o; o >>= 1) d += __shfl_xor_sync(0xffffffffu, d, o);
                float sv = d - g_enorm[c];
                if (sv > best_v || (sv == best_v && c < best_i)) { best_v = sv; best_i = c; }
            }
        }
    }
    if (lane == 0) {
        g_idx[n] = best_i;
        dout[OFF_IDX + n] = (float)best_i;
    }
}

// ---------------------------------------------------------------- epilogue kernels
__global__ void k_gather(const float* __restrict__ z, const float* __restrict__ emb,
                         float* __restrict__ dout) {
    __shared__ float sred[256];
    int t  = blockIdx.x * blockDim.x + threadIdx.x;
    int nt = gridDim.x * blockDim.x;
    float ls = 0.f;
    for (int e = t; e < TOTAL_ELEMS; e += nt) {
        int p  = e & 1023;
        int c  = (e >> 10) & 255;
        int bb = e >> 18;
        int n  = (bb << 10) + p;
        int code = g_idx[n];
        float zv = z[e];
        float ev = __ldg(emb + (size_t)code * E_DIM + c);
        dout[OFF_ZQ + e] = ev;
        float d = ev - zv;
        ls += d * d;
        atomicAdd(g_embed_sum + (size_t)code * E_DIM + c, zv);
        if (c == 0) atomicAdd(g_enc_sum + code, 1.0f);
    }
    sred[threadIdx.x] = ls;
    __syncthreads();
    for (int s = 128; s; s >>= 1) {
        if (threadIdx.x < s) sred[threadIdx.x] += sred[threadIdx.x + s];
        __syncthreads();
    }
    if (threadIdx.x == 0) atomicAdd(&g_loss, sred[0]);
}

__global__ void k_fin1(const float* __restrict__ cs, float* __restrict__ dout) {
    __shared__ float sn[1024];
    __shared__ float sp[1024];
    int t = threadIdx.x;
    float ln = 0.f, lp = 0.f;
    for (int j = t; j < N_CODES; j += 1024) {
        float es  = g_enc_sum[j];
        float ncs = cs[j] * DECAYF + OMDF * es;
        dout[OFF_CS + j] = ncs;
        ln += ncs;
        float pr = es * (1.0f / (float)N_VECS);
        lp += pr * logf(pr + 1e-10f);
    }
    sn[t] = ln; sp[t] = lp;
    __syncthreads();
    for (int s = 512; s; s >>= 1) {
        if (t < s) { sn[t] += sn[t + s]; sp[t] += sp[t + s]; }
        __syncthreads();
    }
    if (t == 0) {
        g_n = sn[0];
        dout[OFF_PERP] = expf(-sp[0]);
        dout[OFF_LOSS] = g_loss * (BETAF / (float)TOTAL_ELEMS);
    }
}

__global__ void k_fin2(const float* __restrict__ ea, float* __restrict__ dout) {
    int i = blockIdx.x * blockDim.x + threadIdx.x;
    if (i >= N_CODES * E_DIM) return;
    int code = i >> 8;
    float nea = ea[i] * DECAYF + OMDF * g_embed_sum[i];
    dout[OFF_EA + i] = nea;
    float ncs = dout[OFF_CS + code];
    float n = g_n;
    float sm = (ncs + EPSF) / (n + (float)N_CODES * EPSF) * n;
    dout[OFF_EMB + i] = nea / sm;
}

// ---------------------------------------------------------------- launch
extern "C" void kernel_launch(void* const* d_in, const int* in_sizes, int n_in,
                              void* d_out, int out_size) {
    const float* z   = (const float*)d_in[0];
    const float* emb = (const float*)d_in[1];
    const float* cs  = (const float*)d_in[2];
    const float* ea  = (const float*)d_in[3];
    float* out = (float*)d_out;

    cudaFuncSetAttribute(k_mma, cudaFuncAttributeMaxDynamicSharedMemorySize, SMEM_TOTAL);

    k_zero<<<1024, 512>>>();
    k_enorm<<<512, 256>>>(emb);
    k_split_z<<<dim3(32, 8, 16), dim3(32, 8)>>>(z);
    k_mma<<<N_VECS / M_BLK, 256, SMEM_TOTAL>>>();
    k_refine<<<N_VECS / 8, 256>>>(emb, out);
    k_gather<<<4096, 256>>>(z, emb, out);
    k_fin1<<<1, 1024>>>(cs, out);
    k_fin2<<<4096, 256>>>(ea, out);
}

// round 15
// speedup vs baseline: 1.2644x; 1.0382x over previous
#include <cuda_runtime.h>
#include <cuda_bf16.h>
#include <cuda_fp16.h>
#include <math.h>
#include <stdint.h>

// ---------------------------------------------------------------- constants
#define TOTAL_ELEMS (16*256*1024)
#define N_CODES 4096
#define E_DIM   256
#define N_VECS  16384
#define DECAYF  0.99f
#define OMDF    0.01f
#define BETAF   0.25f
#define EPSF    1e-5f

#define OFF_LOSS 0
#define OFF_ZQ   1
#define OFF_PERP (1 + TOTAL_ELEMS)
#define OFF_IDX  (2 + TOTAL_ELEMS)
#define OFF_EMB  (2 + TOTAL_ELEMS + N_VECS)
#define OFF_CS   (OFF_EMB + N_CODES*E_DIM)
#define OFF_EA   (OFF_CS + N_CODES)

// Phase-1 GEMM: block = 64 rows x 256-code chunks (16 chunks), bf16 a0*b0.
// 8 warps, warp tile 64x32. B slices WARP-PRIVATE (per-warp cp.async ring,
// per-warp wait_group). Zero block barriers in the main loop. Chunk-major
// unrolled loop with incremental ring counters, empty-commit tail.
#define M_BLK 64
#define N_CHUNK 256
#define N_CHUNKS 16
#define N_TILES (N_CHUNKS * 8)      // 8 k-tiles of 32 per chunk

// smem layout (bytes from base)
#define A_STRIDE 528                // 256 bf16 = 512B + 16 pad (ldmatrix conflict-free)
#define SOFF_A    0                 // 64 x 528 = 33792
#define SOFF_B    33792             // 3 bufs x 8 warps x 2560 = 61440 (reused for reduce)
#define SMEM_TOTAL 95232            // x2 CTAs = 190.5KB <= 228KB/SM

// ---------------------------------------------------------------- scratch
__device__ __align__(128) __nv_bfloat16 g_zs0[(size_t)N_VECS * E_DIM];
__device__ __align__(128) __nv_bfloat16 g_es0[(size_t)N_CODES * E_DIM];
__device__ __align__(128) float g_zfT[(size_t)N_VECS * E_DIM];   // fp32, n-major
__device__ __align__(128) float g_zn2[N_VECS];                   // ||z_n||^2
__device__ __align__(128) __half g_scores[(size_t)N_VECS * N_CODES];
__device__ __align__(128) float g_rowmax[N_VECS];
__device__ __align__(128) float g_enorm[N_CODES];
__device__ __align__(128) int   g_idx[N_VECS];
__device__ __align__(128) float g_enc_sum[N_CODES];
__device__ __align__(128) float g_embed_sum[N_CODES * E_DIM];
__device__ float g_loss;
__device__ float g_n;
__device__ float g_bmax;

// ---------------------------------------------------------------- asm helpers
__device__ __forceinline__ uint32_t smem_u32(const void* p) {
    uint32_t a;
    asm("{ .reg .u64 t; cvta.to.shared.u64 t, %1; cvt.u32.u64 %0, t; }" : "=r"(a) : "l"(p));
    return a;
}
#define CP16(dst, src)   asm volatile("cp.async.cg.shared.global [%0], [%1], 16;" :: "r"(dst), "l"(src) : "memory")
#define CP_COMMIT()      asm volatile("cp.async.commit_group;" ::: "memory")
#define CP_WAIT1()       asm volatile("cp.async.wait_group 1;" ::: "memory")

#define LDSM_X4(r, addr) asm volatile( \
    "ldmatrix.sync.aligned.m8n8.x4.shared.b16 {%0,%1,%2,%3}, [%4];" \
    : "=r"((r)[0]),"=r"((r)[1]),"=r"((r)[2]),"=r"((r)[3]) : "r"(addr))

#define MMA16816(c, a, b) asm volatile( \
    "mma.sync.aligned.m16n8k16.row.col.f32.bf16.bf16.f32 " \
    "{%0,%1,%2,%3}, {%4,%5,%6,%7}, {%8,%9}, {%0,%1,%2,%3};" \
    : "+f"((c)[0]),"+f"((c)[1]),"+f"((c)[2]),"+f"((c)[3]) \
    : "r"((a)[0]),"r"((a)[1]),"r"((a)[2]),"r"((a)[3]), "r"((b)[0]),"r"((b)[1]))

// ---------------------------------------------------------------- prep kernels
__global__ void k_zero() {
    int t = blockIdx.x * blockDim.x + threadIdx.x;
    int nt = gridDim.x * blockDim.x;
    for (int i = t; i < N_CODES * E_DIM; i += nt) g_embed_sum[i] = 0.f;
    for (int i = t; i < N_CODES; i += nt) g_enc_sum[i] = 0.f;
    for (int i = t; i < N_VECS; i += nt) g_zn2[i] = 0.f;
    if (t == 0) { g_loss = 0.f; g_bmax = 0.f; }
}

// 0.5*||e||^2, bmax, and bf16 conversion of emb in one pass.
__global__ void k_enorm(const float* __restrict__ emb) {
    int warp = (blockIdx.x * blockDim.x + threadIdx.x) >> 5;
    int lane = threadIdx.x & 31;
    if (warp >= N_CODES) return;
    const float* r = emb + warp * E_DIM;
    float s = 0.f;
    #pragma unroll
    for (int c = 0; c < E_DIM; c += 32) {
        float v = r[c + lane];
        s += v * v;
        g_es0[(size_t)warp * E_DIM + c + lane] = __float2bfloat16(v);
    }
    #pragma unroll
    for (int o = 16; o; o >>= 1) s += __shfl_down_sync(0xffffffffu, s, o);
    if (lane == 0) {
        g_enorm[warp] = 0.5f * s;
        atomicMax((int*)&g_bmax, __float_as_int(sqrtf(s)));   // positive floats
    }
}

// z (b, c, p) -> g_zs0 bf16, g_zfT fp32 [n][k]; accumulate ||z_n||^2
__global__ void k_split_z(const float* __restrict__ z) {
    __shared__ float t[32][33];
    int b  = blockIdx.z;
    int c0 = blockIdx.y * 32;
    int p0 = blockIdx.x * 32;
    #pragma unroll
    for (int i = 0; i < 32; i += 8)
        t[threadIdx.y + i][threadIdx.x] =
            z[((size_t)(b * 256 + c0 + threadIdx.y + i)) * 1024 + p0 + threadIdx.x];
    __syncthreads();
    #pragma unroll
    for (int i = 0; i < 32; i += 8) {
        int n = b * 1024 + p0 + threadIdx.y + i;
        int k = c0 + threadIdx.x;
        float v = t[threadIdx.x][threadIdx.y + i];
        size_t o = (size_t)n * E_DIM + k;
        g_zs0[o] = __float2bfloat16(v);
        g_zfT[o] = v;
        float s = v * v;
        #pragma unroll
        for (int of = 16; of; of >>= 1) s += __shfl_down_sync(0xffffffffu, s, of);
        if (threadIdx.x == 0) atomicAdd(g_zn2 + n, s);
    }
}

// ---------------------------------------------------------------- phase 1: approx GEMM
// Warp-private B pipeline; chunk-major unrolled main loop.
__global__ __launch_bounds__(256, 2) void k_mma() {
    extern __shared__ char smem_raw[];
    const uint32_t SB = smem_u32(smem_raw);
    const int tid  = threadIdx.x;
    const int lane = tid & 31;
    const int wid  = tid >> 5;          // warp_n 0..7 (32 codes each)
    const int m0 = blockIdx.x * M_BLK;

    const int a_row = ((lane >> 3) & 1) * 8 + (lane & 7);
    const uint32_t a_res_off = (uint32_t)(a_row * A_STRIDE + ((lane >> 4) & 1) * 16);
    const uint32_t b_loc4 = (uint32_t)((((lane >> 4) & 1) * 8 + (lane & 7)) * 80
                                       + ((lane >> 3) & 1) * 16);

    // per-warp B slice issue into explicit buffer
    auto issue_tile = [&](int tt, int buf) {
        int kt    = tt & 7;
        int chunk = tt >> 3;
        uint32_t wB = SB + SOFF_B + buf * 20480 + wid * 2560;
        #pragma unroll
        for (int i = 0; i < 4; ++i) {
            int j = lane + i * 32;           // 0..127
            int code = j >> 2, seg = j & 3;
            const char* src = (const char*)(g_es0
                + (size_t)(chunk * N_CHUNK + wid * 32 + code) * E_DIM + kt * 32 + seg * 8);
            CP16(wB + code * 80 + seg * 16, src);
        }
        CP_COMMIT();
    };

    // A panel (bf16, 64 rows) cooperative load (group 0 per warp)
    #pragma unroll
    for (int i = 0; i < 8; ++i) {
        int li = tid + i * 256;              // 0..2047
        int row = li >> 5, seg = li & 31;
        const char* src = (const char*)(g_zs0 + (size_t)(m0 + row) * E_DIM + seg * 8);
        CP16(SB + SOFF_A + row * A_STRIDE + seg * 16, src);
    }
    CP_COMMIT();
    issue_tile(0, 0);
    issue_tile(1, 1);

    float acc[4][4][4];
    #pragma unroll
    for (int mt = 0; mt < 4; ++mt)
        #pragma unroll
        for (int nt = 0; nt < 4; ++nt)
            #pragma unroll
            for (int j = 0; j < 4; ++j) acc[mt][nt][j] = 0.f;

    float smax[8];
    #pragma unroll
    for (int s = 0; s < 8; ++s) smax[s] = -1e30f;

    // Peel: A (+ tile 0) complete, publish A across warps (only block barrier).
    CP_WAIT1();
    __syncthreads();

    int cbuf = 0;   // compute buffer (tt % 3)
    int ibuf = 2;   // issue buffer ((tt+2) % 3)

    for (int chunk = 0; chunk < N_CHUNKS; ++chunk) {
        float ens_v = __ldg(g_enorm + chunk * N_CHUNK + wid * 32 + lane);

        #pragma unroll
        for (int kt = 0; kt < 8; ++kt) {
            int tt = chunk * 8 + kt;
            CP_WAIT1();                       // own stream: tile tt's slice ready
            if (tt + 2 < N_TILES) issue_tile(tt + 2, ibuf);
            else CP_COMMIT();                 // empty group keeps wait accounting uniform
            ibuf = (ibuf == 2) ? 0 : ibuf + 1;

            uint32_t bbase4 = SB + SOFF_B + cbuf * 20480 + wid * 2560 + b_loc4;
            cbuf = (cbuf == 2) ? 0 : cbuf + 1;

            #pragma unroll
            for (int km = 0; km < 2; ++km) {
                uint32_t bf[4][2];
                #pragma unroll
                for (int p = 0; p < 2; ++p) {
                    uint32_t r[4];
                    LDSM_X4(r, bbase4 + p * 1280 + km * 32);   // 16 n-rows x 2 k-halves
                    bf[2*p][0] = r[0]; bf[2*p][1] = r[1];
                    bf[2*p+1][0] = r[2]; bf[2*p+1][1] = r[3];
                }
                #pragma unroll
                for (int mt = 0; mt < 4; ++mt) {
                    uint32_t af[4];
                    LDSM_X4(af, SB + SOFF_A + a_res_off
                                + mt * (16 * A_STRIDE) + kt * 64 + km * 32);
                    #pragma unroll
                    for (int nt = 0; nt < 4; ++nt)
                        MMA16816(acc[mt][nt], af, bf[nt]);
                }
            }
        }

        // ---- chunk epilogue: enorm via shuffle, reg-max, fp16 store ----
        float ensl[4][2];
        #pragma unroll
        for (int nt = 0; nt < 4; ++nt) {
            int li = nt * 8 + (lane & 3) * 2;
            ensl[nt][0] = __shfl_sync(0xffffffffu, ens_v, li);
            ensl[nt][1] = __shfl_sync(0xffffffffu, ens_v, li + 1);
        }
        #pragma unroll
        for (int mt = 0; mt < 4; ++mt) {
            int row = m0 + mt * 16 + (lane >> 2);
            #pragma unroll
            for (int nt = 0; nt < 4; ++nt) {
                int col = chunk * N_CHUNK + wid * 32 + nt * 8 + (lane & 3) * 2;
                float v0 = acc[mt][nt][0] - ensl[nt][0];
                float v1 = acc[mt][nt][1] - ensl[nt][1];
                float v2 = acc[mt][nt][2] - ensl[nt][0];
                float v3 = acc[mt][nt][3] - ensl[nt][1];
                smax[mt * 2]     = fmaxf(smax[mt * 2],     fmaxf(v0, v1));
                smax[mt * 2 + 1] = fmaxf(smax[mt * 2 + 1], fmaxf(v2, v3));
                *(__half2*)(g_scores + (size_t)row * N_CODES + col) =
                    __floats2half2_rn(v0, v1);
                *(__half2*)(g_scores + (size_t)(row + 8) * N_CODES + col) =
                    __floats2half2_rn(v2, v3);
                acc[mt][nt][0] = 0.f; acc[mt][nt][1] = 0.f;
                acc[mt][nt][2] = 0.f; acc[mt][nt][3] = 0.f;
            }
        }
    }

    // ---- single final per-row max reduction (reuse B smem) ----
    __syncthreads();
    float* redmax = (float*)(smem_raw + SOFF_B);    // 64*32 floats = 8KB
    #pragma unroll
    for (int s = 0; s < 8; ++s) {
        int mt = s >> 1, half = s & 1;
        int row = mt * 16 + half * 8 + (lane >> 2);
        redmax[row * 32 + wid * 4 + (lane & 3)] = smax[s];
    }
    __syncthreads();
    if (tid < M_BLK) {
        float m = redmax[tid * 32];
        #pragma unroll
        for (int t = 1; t < 32; ++t) m = fmaxf(m, redmax[tid * 32 + t]);
        g_rowmax[m0 + tid] = m;
    }
}

// ---------------------------------------------------------------- phase 2: single-pass exact rescore
__global__ __launch_bounds__(256) void k_refine(const float* __restrict__ emb,
                                                float* __restrict__ dout) {
    int w = threadIdx.x >> 5;
    int lane = threadIdx.x & 31;
    int n = blockIdx.x * 8 + w;
    if (n >= N_VECS) return;

    float zr[8];
    #pragma unroll
    for (int j = 0; j < 8; ++j)
        zr[j] = g_zfT[(size_t)n * E_DIM + lane + 32 * j];

    // realized rounding error is RMS ~ u*sqrt(2)*||z .* e||_2 ~= 0.1; this is
    // ~6 sigma of worst-realistic with 3x headroom (inputs are deterministic).
    float margin = 0.006f * sqrtf(g_zn2[n]) * g_bmax + 0.4f;
    float thr = g_rowmax[n] - margin;

    const __half2* sr = (const __half2*)(g_scores + (size_t)n * N_CODES);

    float best_v = -1e30f;
    int   best_i = 0x7fffffff;

    for (int i = 0; i < 64; ++i) {
        float2 v = __half22float2(sr[i * 32 + lane]);
        unsigned mb0 = __ballot_sync(0xffffffffu, v.x >= thr);
        unsigned mb1 = __ballot_sync(0xffffffffu, v.y >= thr);
        unsigned mm = mb0 | mb1;
        while (mm) {
            int l = __ffs(mm) - 1;
            mm &= mm - 1;
            #pragma unroll
            for (int e = 0; e < 2; ++e) {
                if (!((e ? mb1 : mb0) >> l & 1)) continue;
                int c = i * 64 + l * 2 + e;
                const float* er = emb + (size_t)c * E_DIM;
                float d = 0.f;
                #pragma unroll
                for (int j = 0; j < 8; ++j)
                    d = fmaf(zr[j], er[lane + 32 * j], d);
                #pragma unroll
                for (int o = 16; o; o >>= 1) d += __shfl_xor_sync(0xffffffffu, d, o);
                float sv = d - g_enorm[c];
                if (sv > best_v || (sv == best_v && c < best_i)) { best_v = sv; best_i = c; }
            }
        }
    }
    if (lane == 0) {
        g_idx[n] = best_i;
        dout[OFF_IDX + n] = (float)best_i;
    }
}

// ---------------------------------------------------------------- epilogue kernels
__global__ void k_gather(const float* __restrict__ z, const float* __restrict__ emb,
                         float* __restrict__ dout) {
    __shared__ float sred[256];
    int t  = blockIdx.x * blockDim.x + threadIdx.x;
    int nt = gridDim.x * blockDim.x;
    float ls = 0.f;
    for (int e = t; e < TOTAL_ELEMS; e += nt) {
        int p  = e & 1023;
        int c  = (e >> 10) & 255;
        int bb = e >> 18;
        int n  = (bb << 10) + p;
        int code = g_idx[n];
        float zv = z[e];
        float ev = __ldg(emb + (size_t)code * E_DIM + c);
        dout[OFF_ZQ + e] = ev;
        float d = ev - zv;
        ls += d * d;
        atomicAdd(g_embed_sum + (size_t)code * E_DIM + c, zv);
        if (c == 0) atomicAdd(g_enc_sum + code, 1.0f);
    }
    sred[threadIdx.x] = ls;
    __syncthreads();
    for (int s = 128; s; s >>= 1) {
        if (threadIdx.x < s) sred[threadIdx.x] += sred[threadIdx.x + s];
        __syncthreads();
    }
    if (threadIdx.x == 0) atomicAdd(&g_loss, sred[0]);
}

__global__ void k_fin1(const float* __restrict__ cs, float* __restrict__ dout) {
    __shared__ float sn[1024];
    __shared__ float sp[1024];
    int t = threadIdx.x;
    float ln = 0.f, lp = 0.f;
    for (int j = t; j < N_CODES; j += 1024) {
        float es  = g_enc_sum[j];
        float ncs = cs[j] * DECAYF + OMDF * es;
        dout[OFF_CS + j] = ncs;
        ln += ncs;
        float pr = es * (1.0f / (float)N_VECS);
        lp += pr * logf(pr + 1e-10f);
    }
    sn[t] = ln; sp[t] = lp;
    __syncthreads();
    for (int s = 512; s; s >>= 1) {
        if (t < s) { sn[t] += sn[t + s]; sp[t] += sp[t + s]; }
        __syncthreads();
    }
    if (t == 0) {
        g_n = sn[0];
        dout[OFF_PERP] = expf(-sp[0]);
        dout[OFF_LOSS] = g_loss * (BETAF / (float)TOTAL_ELEMS);
    }
}

__global__ void k_fin2(const float* __restrict__ ea, float* __restrict__ dout) {
    int i = blockIdx.x * blockDim.x + threadIdx.x;
    if (i >= N_CODES * E_DIM) return;
    int code = i >> 8;
    float nea = ea[i] * DECAYF + OMDF * g_embed_sum[i];
    dout[OFF_EA + i] = nea;
    float ncs = dout[OFF_CS + code];
    float n = g_n;
    float sm = (ncs + EPSF) / (n + (float)N_CODES * EPSF) * n;
    dout[OFF_EMB + i] = nea / sm;
}

// ---------------------------------------------------------------- launch
extern "C" void kernel_launch(void* const* d_in, const int* in_sizes, int n_in,
                              void* d_out, int out_size) {
    const float* z   = (const float*)d_in[0];
    const float* emb = (const float*)d_in[1];
    const float* cs  = (const float*)d_in[2];
    const float* ea  = (const float*)d_in[3];
    float* out = (float*)d_out;

    cudaFuncSetAttribute(k_mma, cudaFuncAttributeMaxDynamicSharedMemorySize, SMEM_TOTAL);

    k_zero<<<1024, 512>>>();
    k_enorm<<<512, 256>>>(emb);
    k_split_z<<<dim3(32, 8, 16), dim3(32, 8)>>>(z);
    k_mma<<<N_VECS / M_BLK, 256, SMEM_TOTAL>>>();
    k_refine<<<N_VECS / 8, 256>>>(emb, out);
    k_gather<<<4096, 256>>>(z, emb, out);
    k_fin1<<<1, 1024>>>(cs, out);
    k_fin2<<<4096, 256>>>(ea, out);
}

// round 16
// speedup vs baseline: 1.4179x; 1.1214x over previous
#include <cuda_runtime.h>
#include <cuda_bf16.h>
#include <cuda_fp16.h>
#include <math.h>
#include <stdint.h>

// ---------------------------------------------------------------- constants
#define TOTAL_ELEMS (16*256*1024)
#define N_CODES 4096
#define E_DIM   256
#define N_VECS  16384
#define DECAYF  0.99f
#define OMDF    0.01f
#define BETAF   0.25f
#define EPSF    1e-5f

#define OFF_LOSS 0
#define OFF_ZQ   1
#define OFF_PERP (1 + TOTAL_ELEMS)
#define OFF_IDX  (2 + TOTAL_ELEMS)
#define OFF_EMB  (2 + TOTAL_ELEMS + N_VECS)
#define OFF_CS   (OFF_EMB + N_CODES*E_DIM)
#define OFF_EA   (OFF_CS + N_CODES)

// Phase-1 GEMM: block = 64 rows x 256-code chunks (16 chunks), bf16 a0*b0.
// 8 warps, warp tile 64x32. B slices WARP-PRIVATE (per-warp cp.async ring,
// per-warp wait_group). Zero block barriers in the main loop.
#define M_BLK 64
#define N_CHUNK 256
#define N_CHUNKS 16
#define N_TILES (N_CHUNKS * 8)      // 8 k-tiles of 32 per chunk

// smem layout (bytes from base)
#define A_STRIDE 528                // 256 bf16 = 512B + 16 pad (ldmatrix conflict-free)
#define SOFF_A    0                 // 64 x 528 = 33792
#define SOFF_B    33792             // 3 bufs x 8 warps x 2560 = 61440 (reused for reduce)
#define SMEM_TOTAL 95232            // x2 CTAs = 190.5KB <= 228KB/SM

// ---------------------------------------------------------------- scratch
__device__ __align__(128) __nv_bfloat16 g_zs0[(size_t)N_VECS * E_DIM];
__device__ __align__(128) __nv_bfloat16 g_es0[(size_t)N_CODES * E_DIM];
__device__ __align__(128) float g_zfT[(size_t)N_VECS * E_DIM];   // fp32, n-major
__device__ __align__(128) float g_zn2[N_VECS];                   // ||z_n||^2
__device__ __align__(128) __half g_scores[(size_t)N_VECS * N_CODES];
__device__ __align__(128) float g_rowmax[N_VECS];
__device__ __align__(128) float g_enorm[N_CODES];
__device__ __align__(128) int   g_idx[N_VECS];
__device__ __align__(128) float g_enc_sum[N_CODES];
__device__ __align__(128) float g_embed_sum[N_CODES * E_DIM];
__device__ float g_loss;
__device__ float g_n;
__device__ float g_bmax;

// ---------------------------------------------------------------- asm helpers
__device__ __forceinline__ uint32_t smem_u32(const void* p) {
    uint32_t a;
    asm("{ .reg .u64 t; cvta.to.shared.u64 t, %1; cvt.u32.u64 %0, t; }" : "=r"(a) : "l"(p));
    return a;
}
#define CP16(dst, src)   asm volatile("cp.async.cg.shared.global [%0], [%1], 16;" :: "r"(dst), "l"(src) : "memory")
#define CP_COMMIT()      asm volatile("cp.async.commit_group;" ::: "memory")
#define CP_WAIT1()       asm volatile("cp.async.wait_group 1;" ::: "memory")

#define LDSM_X4(r, addr) asm volatile( \
    "ldmatrix.sync.aligned.m8n8.x4.shared.b16 {%0,%1,%2,%3}, [%4];" \
    : "=r"((r)[0]),"=r"((r)[1]),"=r"((r)[2]),"=r"((r)[3]) : "r"(addr))

#define MMA16816(c, a, b) asm volatile( \
    "mma.sync.aligned.m16n8k16.row.col.f32.bf16.bf16.f32 " \
    "{%0,%1,%2,%3}, {%4,%5,%6,%7}, {%8,%9}, {%0,%1,%2,%3};" \
    : "+f"((c)[0]),"+f"((c)[1]),"+f"((c)[2]),"+f"((c)[3]) \
    : "r"((a)[0]),"r"((a)[1]),"r"((a)[2]),"r"((a)[3]), "r"((b)[0]),"r"((b)[1]))

// ---------------------------------------------------------------- prep kernels
__global__ void k_zero() {
    int t = blockIdx.x * blockDim.x + threadIdx.x;
    int nt = gridDim.x * blockDim.x;
    for (int i = t; i < N_CODES * E_DIM; i += nt) g_embed_sum[i] = 0.f;
    for (int i = t; i < N_CODES; i += nt) g_enc_sum[i] = 0.f;
    for (int i = t; i < N_VECS; i += nt) g_zn2[i] = 0.f;
    if (t == 0) { g_loss = 0.f; g_bmax = 0.f; }
}

// 0.5*||e||^2, bmax, and bf16 conversion of emb in one pass.
__global__ void k_enorm(const float* __restrict__ emb) {
    int warp = (blockIdx.x * blockDim.x + threadIdx.x) >> 5;
    int lane = threadIdx.x & 31;
    if (warp >= N_CODES) return;
    const float* r = emb + warp * E_DIM;
    float s = 0.f;
    #pragma unroll
    for (int c = 0; c < E_DIM; c += 32) {
        float v = r[c + lane];
        s += v * v;
        g_es0[(size_t)warp * E_DIM + c + lane] = __float2bfloat16(v);
    }
    #pragma unroll
    for (int o = 16; o; o >>= 1) s += __shfl_down_sync(0xffffffffu, s, o);
    if (lane == 0) {
        g_enorm[warp] = 0.5f * s;
        atomicMax((int*)&g_bmax, __float_as_int(sqrtf(s)));   // positive floats
    }
}

// z (b, c, p) -> g_zs0 bf16, g_zfT fp32 [n][k]; accumulate ||z_n||^2
__global__ void k_split_z(const float* __restrict__ z) {
    __shared__ float t[32][33];
    int b  = blockIdx.z;
    int c0 = blockIdx.y * 32;
    int p0 = blockIdx.x * 32;
    #pragma unroll
    for (int i = 0; i < 32; i += 8)
        t[threadIdx.y + i][threadIdx.x] =
            z[((size_t)(b * 256 + c0 + threadIdx.y + i)) * 1024 + p0 + threadIdx.x];
    __syncthreads();
    #pragma unroll
    for (int i = 0; i < 32; i += 8) {
        int n = b * 1024 + p0 + threadIdx.y + i;
        int k = c0 + threadIdx.x;
        float v = t[threadIdx.x][threadIdx.y + i];
        size_t o = (size_t)n * E_DIM + k;
        g_zs0[o] = __float2bfloat16(v);
        g_zfT[o] = v;
        float s = v * v;
        #pragma unroll
        for (int of = 16; of; of >>= 1) s += __shfl_down_sync(0xffffffffu, s, of);
        if (threadIdx.x == 0) atomicAdd(g_zn2 + n, s);
    }
}

// ---------------------------------------------------------------- phase 1: approx GEMM
// Warp-private B pipeline; chunk-major unrolled main loop. (Unchanged from R15.)
__global__ __launch_bounds__(256, 2) void k_mma() {
    extern __shared__ char smem_raw[];
    const uint32_t SB = smem_u32(smem_raw);
    const int tid  = threadIdx.x;
    const int lane = tid & 31;
    const int wid  = tid >> 5;          // warp_n 0..7 (32 codes each)
    const int m0 = blockIdx.x * M_BLK;

    const int a_row = ((lane >> 3) & 1) * 8 + (lane & 7);
    const uint32_t a_res_off = (uint32_t)(a_row * A_STRIDE + ((lane >> 4) & 1) * 16);
    const uint32_t b_loc4 = (uint32_t)((((lane >> 4) & 1) * 8 + (lane & 7)) * 80
                                       + ((lane >> 3) & 1) * 16);

    auto issue_tile = [&](int tt, int buf) {
        int kt    = tt & 7;
        int chunk = tt >> 3;
        uint32_t wB = SB + SOFF_B + buf * 20480 + wid * 2560;
        #pragma unroll
        for (int i = 0; i < 4; ++i) {
            int j = lane + i * 32;           // 0..127
            int code = j >> 2, seg = j & 3;
            const char* src = (const char*)(g_es0
                + (size_t)(chunk * N_CHUNK + wid * 32 + code) * E_DIM + kt * 32 + seg * 8);
            CP16(wB + code * 80 + seg * 16, src);
        }
        CP_COMMIT();
    };

    #pragma unroll
    for (int i = 0; i < 8; ++i) {
        int li = tid + i * 256;              // 0..2047
        int row = li >> 5, seg = li & 31;
        const char* src = (const char*)(g_zs0 + (size_t)(m0 + row) * E_DIM + seg * 8);
        CP16(SB + SOFF_A + row * A_STRIDE + seg * 16, src);
    }
    CP_COMMIT();
    issue_tile(0, 0);
    issue_tile(1, 1);

    float acc[4][4][4];
    #pragma unroll
    for (int mt = 0; mt < 4; ++mt)
        #pragma unroll
        for (int nt = 0; nt < 4; ++nt)
            #pragma unroll
            for (int j = 0; j < 4; ++j) acc[mt][nt][j] = 0.f;

    float smax[8];
    #pragma unroll
    for (int s = 0; s < 8; ++s) smax[s] = -1e30f;

    CP_WAIT1();
    __syncthreads();

    int cbuf = 0;
    int ibuf = 2;

    for (int chunk = 0; chunk < N_CHUNKS; ++chunk) {
        float ens_v = __ldg(g_enorm + chunk * N_CHUNK + wid * 32 + lane);

        #pragma unroll
        for (int kt = 0; kt < 8; ++kt) {
            int tt = chunk * 8 + kt;
            CP_WAIT1();
            if (tt + 2 < N_TILES) issue_tile(tt + 2, ibuf);
            else CP_COMMIT();
            ibuf = (ibuf == 2) ? 0 : ibuf + 1;

            uint32_t bbase4 = SB + SOFF_B + cbuf * 20480 + wid * 2560 + b_loc4;
            cbuf = (cbuf == 2) ? 0 : cbuf + 1;

            #pragma unroll
            for (int km = 0; km < 2; ++km) {
                uint32_t bf[4][2];
                #pragma unroll
                for (int p = 0; p < 2; ++p) {
                    uint32_t r[4];
                    LDSM_X4(r, bbase4 + p * 1280 + km * 32);
                    bf[2*p][0] = r[0]; bf[2*p][1] = r[1];
                    bf[2*p+1][0] = r[2]; bf[2*p+1][1] = r[3];
                }
                #pragma unroll
                for (int mt = 0; mt < 4; ++mt) {
                    uint32_t af[4];
                    LDSM_X4(af, SB + SOFF_A + a_res_off
                                + mt * (16 * A_STRIDE) + kt * 64 + km * 32);
                    #pragma unroll
                    for (int nt = 0; nt < 4; ++nt)
                        MMA16816(acc[mt][nt], af, bf[nt]);
                }
            }
        }

        float ensl[4][2];
        #pragma unroll
        for (int nt = 0; nt < 4; ++nt) {
            int li = nt * 8 + (lane & 3) * 2;
            ensl[nt][0] = __shfl_sync(0xffffffffu, ens_v, li);
            ensl[nt][1] = __shfl_sync(0xffffffffu, ens_v, li + 1);
        }
        #pragma unroll
        for (int mt = 0; mt < 4; ++mt) {
            int row = m0 + mt * 16 + (lane >> 2);
            #pragma unroll
            for (int nt = 0; nt < 4; ++nt) {
                int col = chunk * N_CHUNK + wid * 32 + nt * 8 + (lane & 3) * 2;
                float v0 = acc[mt][nt][0] - ensl[nt][0];
                float v1 = acc[mt][nt][1] - ensl[nt][1];
                float v2 = acc[mt][nt][2] - ensl[nt][0];
                float v3 = acc[mt][nt][3] - ensl[nt][1];
                smax[mt * 2]     = fmaxf(smax[mt * 2],     fmaxf(v0, v1));
                smax[mt * 2 + 1] = fmaxf(smax[mt * 2 + 1], fmaxf(v2, v3));
                *(__half2*)(g_scores + (size_t)row * N_CODES + col) =
                    __floats2half2_rn(v0, v1);
                *(__half2*)(g_scores + (size_t)(row + 8) * N_CODES + col) =
                    __floats2half2_rn(v2, v3);
                acc[mt][nt][0] = 0.f; acc[mt][nt][1] = 0.f;
                acc[mt][nt][2] = 0.f; acc[mt][nt][3] = 0.f;
            }
        }
    }

    __syncthreads();
    float* redmax = (float*)(smem_raw + SOFF_B);    // 64*32 floats = 8KB
    #pragma unroll
    for (int s = 0; s < 8; ++s) {
        int mt = s >> 1, half = s & 1;
        int row = mt * 16 + half * 8 + (lane >> 2);
        redmax[row * 32 + wid * 4 + (lane & 3)] = smax[s];
    }
    __syncthreads();
    if (tid < M_BLK) {
        float m = redmax[tid * 32];
        #pragma unroll
        for (int t = 1; t < 32; ++t) m = fmaxf(m, redmax[tid * 32 + t]);
        g_rowmax[m0 + tid] = m;
    }
}

// ---------------------------------------------------------------- phase 2: exact rescore
// Warp per row. Each LANE privately scans a contiguous 128-code segment via
// 16 x uint4 loads (MLP=16, no ballots in scan), building a 128-bit candidate
// mask. Then one ballot + shuffle broadcast, exact fp32 rescore of candidates.
__global__ __launch_bounds__(256) void k_refine(const float* __restrict__ emb,
                                                float* __restrict__ dout) {
    int w = threadIdx.x >> 5;
    int lane = threadIdx.x & 31;
    int n = blockIdx.x * 8 + w;
    if (n >= N_VECS) return;

    float zr[8];
    #pragma unroll
    for (int j = 0; j < 8; ++j)
        zr[j] = g_zfT[(size_t)n * E_DIM + lane + 32 * j];

    float margin = 0.006f * sqrtf(g_zn2[n]) * g_bmax + 0.4f;
    float thr = g_rowmax[n] - margin;

    // lane's segment: codes [lane*128, lane*128+128) = 256B, 16 x uint4
    const uint4* rp = (const uint4*)(g_scores + (size_t)n * N_CODES) + lane * 16;
    unsigned long long cm0 = 0ull, cm1 = 0ull;
    #pragma unroll
    for (int q = 0; q < 16; ++q) {
        uint4 u = __ldg(rp + q);
        uint32_t ws[4] = {u.x, u.y, u.z, u.w};
        unsigned long long bits = 0ull;
        #pragma unroll
        for (int wd = 0; wd < 4; ++wd) {
            float2 f = __half22float2(*(const __half2*)&ws[wd]);
            if (f.x >= thr) bits |= 1ull << (wd * 2);
            if (f.y >= thr) bits |= 1ull << (wd * 2 + 1);
        }
        if (q < 8) cm0 |= bits << (q * 8);
        else       cm1 |= bits << ((q - 8) * 8);
    }

    float best_v = -1e30f;
    int   best_i = 0x7fffffff;

    unsigned any = __ballot_sync(0xffffffffu, (cm0 | cm1) != 0ull);
    while (any) {
        int l = __ffs(any) - 1;
        any &= any - 1;
        unsigned long long m0 = __shfl_sync(0xffffffffu, cm0, l);
        unsigned long long m1 = __shfl_sync(0xffffffffu, cm1, l);
        #pragma unroll
        for (int h = 0; h < 2; ++h) {
            unsigned long long mm = h ? m1 : m0;
            int cbase = l * 128 + h * 64;
            while (mm) {
                int b = __ffsll((long long)mm) - 1;
                mm &= mm - 1;
                int c = cbase + b;
                const float* er = emb + (size_t)c * E_DIM;
                float d = 0.f;
                #pragma unroll
                for (int j = 0; j < 8; ++j)
                    d = fmaf(zr[j], er[lane + 32 * j], d);
                #pragma unroll
                for (int o = 16; o; o >>= 1) d += __shfl_xor_sync(0xffffffffu, d, o);
                float sv = d - g_enorm[c];
                if (sv > best_v || (sv == best_v && c < best_i)) { best_v = sv; best_i = c; }
            }
        }
    }
    if (lane == 0) {
        g_idx[n] = best_i;
        dout[OFF_IDX + n] = (float)best_i;
    }
}

// ---------------------------------------------------------------- epilogue kernels
__global__ void k_gather(const float* __restrict__ z, const float* __restrict__ emb,
                         float* __restrict__ dout) {
    __shared__ float sred[256];
    int t  = blockIdx.x * blockDim.x + threadIdx.x;
    int nt = gridDim.x * blockDim.x;
    float ls = 0.f;
    for (int e = t; e < TOTAL_ELEMS; e += nt) {
        int p  = e & 1023;
        int c  = (e >> 10) & 255;
        int bb = e >> 18;
        int n  = (bb << 10) + p;
        int code = g_idx[n];
        float zv = z[e];
        float ev = __ldg(emb + (size_t)code * E_DIM + c);
        dout[OFF_ZQ + e] = ev;
        float d = ev - zv;
        ls += d * d;
        atomicAdd(g_embed_sum + (size_t)code * E_DIM + c, zv);
        if (c == 0) atomicAdd(g_enc_sum + code, 1.0f);
    }
    sred[threadIdx.x] = ls;
    __syncthreads();
    for (int s = 128; s; s >>= 1) {
        if (threadIdx.x < s) sred[threadIdx.x] += sred[threadIdx.x + s];
        __syncthreads();
    }
    if (threadIdx.x == 0) atomicAdd(&g_loss, sred[0]);
}

__global__ void k_fin1(const float* __restrict__ cs, float* __restrict__ dout) {
    __shared__ float sn[1024];
    __shared__ float sp[1024];
    int t = threadIdx.x;
    float ln = 0.f, lp = 0.f;
    for (int j = t; j < N_CODES; j += 1024) {
        float es  = g_enc_sum[j];
        float ncs = cs[j] * DECAYF + OMDF * es;
        dout[OFF_CS + j] = ncs;
        ln += ncs;
        float pr = es * (1.0f / (float)N_VECS);
        lp += pr * logf(pr + 1e-10f);
    }
    sn[t] = ln; sp[t] = lp;
    __syncthreads();
    for (int s = 512; s; s >>= 1) {
        if (t < s) { sn[t] += sn[t + s]; sp[t] += sp[t + s]; }
        __syncthreads();
    }
    if (t == 0) {
        g_n = sn[0];
        dout[OFF_PERP] = expf(-sp[0]);
        dout[OFF_LOSS] = g_loss * (BETAF / (float)TOTAL_ELEMS);
    }
}

__global__ void k_fin2(const float* __restrict__ ea, float* __restrict__ dout) {
    int i = blockIdx.x * blockDim.x + threadIdx.x;
    if (i >= N_CODES * E_DIM) return;
    int code = i >> 8;
    float nea = ea[i] * DECAYF + OMDF * g_embed_sum[i];
    dout[OFF_EA + i] = nea;
    float ncs = dout[OFF_CS + code];
    float n = g_n;
    float sm = (ncs + EPSF) / (n + (float)N_CODES * EPSF) * n;
    dout[OFF_EMB + i] = nea / sm;
}

// ---------------------------------------------------------------- launch
extern "C" void kernel_launch(void* const* d_in, const int* in_sizes, int n_in,
                              void* d_out, int out_size) {
    const float* z   = (const float*)d_in[0];
    const float* emb = (const float*)d_in[1];
    const float* cs  = (const float*)d_in[2];
    const float* ea  = (const float*)d_in[3];
    float* out = (float*)d_out;

    cudaFuncSetAttribute(k_mma, cudaFuncAttributeMaxDynamicSharedMemorySize, SMEM_TOTAL);

    k_zero<<<1024, 512>>>();
    k_enorm<<<512, 256>>>(emb);
    k_split_z<<<dim3(32, 8, 16), dim3(32, 8)>>>(z);
    k_mma<<<N_VECS / M_BLK, 256, SMEM_TOTAL>>>();
    k_refine<<<N_VECS / 8, 256>>>(emb, out);
    k_gather<<<4096, 256>>>(z, emb, out);
    k_fin1<<<1, 1024>>>(cs, out);
    k_fin2<<<4096, 256>>>(ea, out);
}

// round 17
// speedup vs baseline: 1.5833x; 1.1167x over previous
#include <cuda_runtime.h>
#include <cuda_bf16.h>
#include <cuda_fp16.h>
#include <math.h>
#include <stdint.h>

// ---------------------------------------------------------------- constants
#define TOTAL_ELEMS (16*256*1024)
#define N_CODES 4096
#define E_DIM   256
#define N_VECS  16384
#define DECAYF  0.99f
#define OMDF    0.01f
#define BETAF   0.25f
#define EPSF    1e-5f

#define OFF_LOSS 0
#define OFF_ZQ   1
#define OFF_PERP (1 + TOTAL_ELEMS)
#define OFF_IDX  (2 + TOTAL_ELEMS)
#define OFF_EMB  (2 + TOTAL_ELEMS + N_VECS)
#define OFF_CS   (OFF_EMB + N_CODES*E_DIM)
#define OFF_EA   (OFF_CS + N_CODES)

// Phase-1 GEMM: block = 64 rows x 256-code chunks (16 chunks), bf16 a0*b0.
// 8 warps, warp tile 64x32. B slices WARP-PRIVATE (per-warp cp.async ring,
// per-warp wait_group). Zero block barriers in the main loop.
// B slots carry the sigma permutation (swap bits[4:3]<->[2:1]) so the score
// epilogue stores coalesced uint4 (8 contiguous codes per lane).
#define M_BLK 64
#define N_CHUNK 256
#define N_CHUNKS 16
#define N_TILES (N_CHUNKS * 8)      // 8 k-tiles of 32 per chunk

// smem layout (bytes from base)
#define A_STRIDE 528                // 256 bf16 = 512B + 16 pad (ldmatrix conflict-free)
#define SOFF_A    0                 // 64 x 528 = 33792
#define SOFF_B    33792             // 3 bufs x 8 warps x 2560 = 61440 (reused for reduce)
#define SMEM_TOTAL 95232            // x2 CTAs = 190.5KB <= 228KB/SM

// ---------------------------------------------------------------- scratch
__device__ __align__(128) __nv_bfloat16 g_zs0[(size_t)N_VECS * E_DIM];
__device__ __align__(128) __nv_bfloat16 g_es0[(size_t)N_CODES * E_DIM];
__device__ __align__(128) float g_zfT[(size_t)N_VECS * E_DIM];   // fp32, n-major
__device__ __align__(128) float g_zn2[N_VECS];                   // ||z_n||^2
__device__ __align__(128) __half g_scores[(size_t)N_VECS * N_CODES];
__device__ __align__(128) float g_rowmax[N_VECS];
__device__ __align__(128) float g_enorm[N_CODES];
__device__ __align__(128) int   g_idx[N_VECS];
__device__ __align__(128) float g_enc_sum[N_CODES];
__device__ __align__(128) float g_embed_sum[N_CODES * E_DIM];
__device__ float g_loss;
__device__ float g_n;
__device__ float g_bmax;

// ---------------------------------------------------------------- asm helpers
__device__ __forceinline__ uint32_t smem_u32(const void* p) {
    uint32_t a;
    asm("{ .reg .u64 t; cvta.to.shared.u64 t, %1; cvt.u32.u64 %0, t; }" : "=r"(a) : "l"(p));
    return a;
}
#define CP16(dst, src)   asm volatile("cp.async.cg.shared.global [%0], [%1], 16;" :: "r"(dst), "l"(src) : "memory")
#define CP_COMMIT()      asm volatile("cp.async.commit_group;" ::: "memory")
#define CP_WAIT1()       asm volatile("cp.async.wait_group 1;" ::: "memory")

#define LDSM_X4(r, addr) asm volatile( \
    "ldmatrix.sync.aligned.m8n8.x4.shared.b16 {%0,%1,%2,%3}, [%4];" \
    : "=r"((r)[0]),"=r"((r)[1]),"=r"((r)[2]),"=r"((r)[3]) : "r"(addr))

#define MMA16816(c, a, b) asm volatile( \
    "mma.sync.aligned.m16n8k16.row.col.f32.bf16.bf16.f32 " \
    "{%0,%1,%2,%3}, {%4,%5,%6,%7}, {%8,%9}, {%0,%1,%2,%3};" \
    : "+f"((c)[0]),"+f"((c)[1]),"+f"((c)[2]),"+f"((c)[3]) \
    : "r"((a)[0]),"r"((a)[1]),"r"((a)[2]),"r"((a)[3]), "r"((b)[0]),"r"((b)[1]))

// ---------------------------------------------------------------- prep kernels
__global__ void k_zero() {
    int t = blockIdx.x * blockDim.x + threadIdx.x;
    int nt = gridDim.x * blockDim.x;
    for (int i = t; i < N_CODES * E_DIM; i += nt) g_embed_sum[i] = 0.f;
    for (int i = t; i < N_CODES; i += nt) g_enc_sum[i] = 0.f;
    for (int i = t; i < N_VECS; i += nt) g_zn2[i] = 0.f;
    if (t == 0) { g_loss = 0.f; g_bmax = 0.f; }
}

// 0.5*||e||^2, bmax, and bf16 conversion of emb in one pass.
__global__ void k_enorm(const float* __restrict__ emb) {
    int warp = (blockIdx.x * blockDim.x + threadIdx.x) >> 5;
    int lane = threadIdx.x & 31;
    if (warp >= N_CODES) return;
    const float* r = emb + warp * E_DIM;
    float s = 0.f;
    #pragma unroll
    for (int c = 0; c < E_DIM; c += 32) {
        float v = r[c + lane];
        s += v * v;
        g_es0[(size_t)warp * E_DIM + c + lane] = __float2bfloat16(v);
    }
    #pragma unroll
    for (int o = 16; o; o >>= 1) s += __shfl_down_sync(0xffffffffu, s, o);
    if (lane == 0) {
        g_enorm[warp] = 0.5f * s;
        atomicMax((int*)&g_bmax, __float_as_int(sqrtf(s)));   // positive floats
    }
}

// z (b, c, p) -> g_zs0 bf16, g_zfT fp32 [n][k]; accumulate ||z_n||^2
__global__ void k_split_z(const float* __restrict__ z) {
    __shared__ float t[32][33];
    int b  = blockIdx.z;
    int c0 = blockIdx.y * 32;
    int p0 = blockIdx.x * 32;
    #pragma unroll
    for (int i = 0; i < 32; i += 8)
        t[threadIdx.y + i][threadIdx.x] =
            z[((size_t)(b * 256 + c0 + threadIdx.y + i)) * 1024 + p0 + threadIdx.x];
    __syncthreads();
    #pragma unroll
    for (int i = 0; i < 32; i += 8) {
        int n = b * 1024 + p0 + threadIdx.y + i;
        int k = c0 + threadIdx.x;
        float v = t[threadIdx.x][threadIdx.y + i];
        size_t o = (size_t)n * E_DIM + k;
        g_zs0[o] = __float2bfloat16(v);
        g_zfT[o] = v;
        float s = v * v;
        #pragma unroll
        for (int of = 16; of; of >>= 1) s += __shfl_down_sync(0xffffffffu, s, of);
        if (threadIdx.x == 0) atomicAdd(g_zn2 + n, s);
    }
}

// ---------------------------------------------------------------- phase 1: approx GEMM
// Warp-private B pipeline; chunk-major unrolled main loop; sigma-permuted B
// slots -> coalesced uint4 score stores.
__global__ __launch_bounds__(256, 2) void k_mma() {
    extern __shared__ char smem_raw[];
    const uint32_t SB = smem_u32(smem_raw);
    const int tid  = threadIdx.x;
    const int lane = tid & 31;
    const int wid  = tid >> 5;          // warp_n 0..7 (32 codes each)
    const int m0 = blockIdx.x * M_BLK;

    const int a_row = ((lane >> 3) & 1) * 8 + (lane & 7);
    const uint32_t a_res_off = (uint32_t)(a_row * A_STRIDE + ((lane >> 4) & 1) * 16);
    const uint32_t b_loc4 = (uint32_t)((((lane >> 4) & 1) * 8 + (lane & 7)) * 80
                                       + ((lane >> 3) & 1) * 16);

    // sigma(q): swap bits[4:3] <-> bits[2:1] (self-inverse). Slot sigma(q)
    // holds code q, so fragment n-pos p computes against code sigma(p).
    auto issue_tile = [&](int tt, int buf) {
        int kt    = tt & 7;
        int chunk = tt >> 3;
        uint32_t wB = SB + SOFF_B + buf * 20480 + wid * 2560;
        #pragma unroll
        for (int i = 0; i < 4; ++i) {
            int j = lane + i * 32;           // 0..127
            int code = j >> 2, seg = j & 3;
            int slot = ((code >> 1) & 3) * 8 + ((code >> 3) & 3) * 2 + (code & 1);
            const char* src = (const char*)(g_es0
                + (size_t)(chunk * N_CHUNK + wid * 32 + code) * E_DIM + kt * 32 + seg * 8);
            CP16(wB + slot * 80 + seg * 16, src);
        }
        CP_COMMIT();
    };

    // A panel (bf16, 64 rows) cooperative load (group 0 per warp)
    #pragma unroll
    for (int i = 0; i < 8; ++i) {
        int li = tid + i * 256;              // 0..2047
        int row = li >> 5, seg = li & 31;
        const char* src = (const char*)(g_zs0 + (size_t)(m0 + row) * E_DIM + seg * 8);
        CP16(SB + SOFF_A + row * A_STRIDE + seg * 16, src);
    }
    CP_COMMIT();
    issue_tile(0, 0);
    issue_tile(1, 1);

    float acc[4][4][4];
    #pragma unroll
    for (int mt = 0; mt < 4; ++mt)
        #pragma unroll
        for (int nt = 0; nt < 4; ++nt)
            #pragma unroll
            for (int j = 0; j < 4; ++j) acc[mt][nt][j] = 0.f;

    float smax[8];
    #pragma unroll
    for (int s = 0; s < 8; ++s) smax[s] = -1e30f;

    CP_WAIT1();
    __syncthreads();     // publish A (only block barrier before final reduce)

    int cbuf = 0;
    int ibuf = 2;

    for (int chunk = 0; chunk < N_CHUNKS; ++chunk) {
        float ens_v = __ldg(g_enorm + chunk * N_CHUNK + wid * 32 + lane);

        #pragma unroll
        for (int kt = 0; kt < 8; ++kt) {
            int tt = chunk * 8 + kt;
            CP_WAIT1();
            if (tt + 2 < N_TILES) issue_tile(tt + 2, ibuf);
            else CP_COMMIT();
            ibuf = (ibuf == 2) ? 0 : ibuf + 1;

            uint32_t bbase4 = SB + SOFF_B + cbuf * 20480 + wid * 2560 + b_loc4;
            cbuf = (cbuf == 2) ? 0 : cbuf + 1;

            #pragma unroll
            for (int km = 0; km < 2; ++km) {
                uint32_t bf[4][2];
                #pragma unroll
                for (int p = 0; p < 2; ++p) {
                    uint32_t r[4];
                    LDSM_X4(r, bbase4 + p * 1280 + km * 32);
                    bf[2*p][0] = r[0]; bf[2*p][1] = r[1];
                    bf[2*p+1][0] = r[2]; bf[2*p+1][1] = r[3];
                }
                #pragma unroll
                for (int mt = 0; mt < 4; ++mt) {
                    uint32_t af[4];
                    LDSM_X4(af, SB + SOFF_A + a_res_off
                                + mt * (16 * A_STRIDE) + kt * 64 + km * 32);
                    #pragma unroll
                    for (int nt = 0; nt < 4; ++nt)
                        MMA16816(acc[mt][nt], af, bf[nt]);
                }
            }
        }

        // ---- chunk epilogue: permuted cols -> per-lane 8 contiguous codes ----
        // acc[mt][nt][j] corresponds to code (lane&3)*8 + nt*2 + (j&1).
        float ensl[4][2];
        #pragma unroll
        for (int nt = 0; nt < 4; ++nt) {
            int li = (lane & 3) * 8 + nt * 2;
            ensl[nt][0] = __shfl_sync(0xffffffffu, ens_v, li);
            ensl[nt][1] = __shfl_sync(0xffffffffu, ens_v, li + 1);
        }
        int colbase = chunk * N_CHUNK + wid * 32 + (lane & 3) * 8;
        #pragma unroll
        for (int mt = 0; mt < 4; ++mt) {
            #pragma unroll
            for (int jh = 0; jh < 2; ++jh) {
                int row = m0 + mt * 16 + jh * 8 + (lane >> 2);
                uint4 pk;
                uint32_t* hp = (uint32_t*)&pk;
                #pragma unroll
                for (int nt = 0; nt < 4; ++nt) {
                    float v0 = acc[mt][nt][jh * 2]     - ensl[nt][0];
                    float v1 = acc[mt][nt][jh * 2 + 1] - ensl[nt][1];
                    smax[mt * 2 + jh] = fmaxf(smax[mt * 2 + jh], fmaxf(v0, v1));
                    __half2 hh = __floats2half2_rn(v0, v1);
                    hp[nt] = *(uint32_t*)&hh;
                }
                __stcs((uint4*)(g_scores + (size_t)row * N_CODES + colbase), pk);
            }
            #pragma unroll
            for (int nt = 0; nt < 4; ++nt)
                #pragma unroll
                for (int j = 0; j < 4; ++j) acc[mt][nt][j] = 0.f;
        }
    }

    // ---- single final per-row max reduction (reuse B smem) ----
    __syncthreads();
    float* redmax = (float*)(smem_raw + SOFF_B);    // 64*32 floats = 8KB
    #pragma unroll
    for (int s = 0; s < 8; ++s) {
        int mt = s >> 1, half = s & 1;
        int row = mt * 16 + half * 8 + (lane >> 2);
        redmax[row * 32 + wid * 4 + (lane & 3)] = smax[s];
    }
    __syncthreads();
    if (tid < M_BLK) {
        float m = redmax[tid * 32];
        #pragma unroll
        for (int t = 1; t < 32; ++t) m = fmaxf(m, redmax[tid * 32 + t]);
        g_rowmax[m0 + tid] = m;
    }
}

// ---------------------------------------------------------------- phase 2: exact rescore
// Warp per row. Each LANE privately scans a contiguous 128-code segment via
// 16 x uint4 loads (MLP=16), building a 128-bit candidate mask. Then one
// ballot + shuffle broadcast, exact fp32 rescore of candidates.
__global__ __launch_bounds__(256) void k_refine(const float* __restrict__ emb,
                                                float* __restrict__ dout) {
    int w = threadIdx.x >> 5;
    int lane = threadIdx.x & 31;
    int n = blockIdx.x * 8 + w;
    if (n >= N_VECS) return;

    float zr[8];
    #pragma unroll
    for (int j = 0; j < 8; ++j)
        zr[j] = g_zfT[(size_t)n * E_DIM + lane + 32 * j];

    float margin = 0.006f * sqrtf(g_zn2[n]) * g_bmax + 0.4f;
    float thr = g_rowmax[n] - margin;

    // lane's segment: codes [lane*128, lane*128+128) = 256B, 16 x uint4
    const uint4* rp = (const uint4*)(g_scores + (size_t)n * N_CODES) + lane * 16;
    unsigned long long cm0 = 0ull, cm1 = 0ull;
    #pragma unroll
    for (int q = 0; q < 16; ++q) {
        uint4 u = __ldg(rp + q);
        uint32_t ws[4] = {u.x, u.y, u.z, u.w};
        unsigned long long bits = 0ull;
        #pragma unroll
        for (int wd = 0; wd < 4; ++wd) {
            float2 f = __half22float2(*(const __half2*)&ws[wd]);
            if (f.x >= thr) bits |= 1ull << (wd * 2);
            if (f.y >= thr) bits |= 1ull << (wd * 2 + 1);
        }
        if (q < 8) cm0 |= bits << (q * 8);
        else       cm1 |= bits << ((q - 8) * 8);
    }

    float best_v = -1e30f;
    int   best_i = 0x7fffffff;

    unsigned any = __ballot_sync(0xffffffffu, (cm0 | cm1) != 0ull);
    while (any) {
        int l = __ffs(any) - 1;
        any &= any - 1;
        unsigned long long m0 = __shfl_sync(0xffffffffu, cm0, l);
        unsigned long long m1 = __shfl_sync(0xffffffffu, cm1, l);
        #pragma unroll
        for (int h = 0; h < 2; ++h) {
            unsigned long long mm = h ? m1 : m0;
            int cbase = l * 128 + h * 64;
            while (mm) {
                int b = __ffsll((long long)mm) - 1;
                mm &= mm - 1;
                int c = cbase + b;
                const float* er = emb + (size_t)c * E_DIM;
                float d = 0.f;
                #pragma unroll
                for (int j = 0; j < 8; ++j)
                    d = fmaf(zr[j], er[lane + 32 * j], d);
                #pragma unroll
                for (int o = 16; o; o >>= 1) d += __shfl_xor_sync(0xffffffffu, d, o);
                float sv = d - g_enorm[c];
                if (sv > best_v || (sv == best_v && c < best_i)) { best_v = sv; best_i = c; }
            }
        }
    }
    if (lane == 0) {
        g_idx[n] = best_i;
        dout[OFF_IDX + n] = (float)best_i;
    }
}

// ---------------------------------------------------------------- epilogue kernels
__global__ void k_gather(const float* __restrict__ z, const float* __restrict__ emb,
                         float* __restrict__ dout) {
    __shared__ float sred[256];
    int t  = blockIdx.x * blockDim.x + threadIdx.x;
    int nt = gridDim.x * blockDim.x;
    float ls = 0.f;
    for (int e = t; e < TOTAL_ELEMS; e += nt) {
        int p  = e & 1023;
        int c  = (e >> 10) & 255;
        int bb = e >> 18;
        int n  = (bb << 10) + p;
        int code = g_idx[n];
        float zv = z[e];
        float ev = __ldg(emb + (size_t)code * E_DIM + c);
        dout[OFF_ZQ + e] = ev;
        float d = ev - zv;
        ls += d * d;
        atomicAdd(g_embed_sum + (size_t)code * E_DIM + c, zv);
        if (c == 0) atomicAdd(g_enc_sum + code, 1.0f);
    }
    sred[threadIdx.x] = ls;
    __syncthreads();
    for (int s = 128; s; s >>= 1) {
        if (threadIdx.x < s) sred[threadIdx.x] += sred[threadIdx.x + s];
        __syncthreads();
    }
    if (threadIdx.x == 0) atomicAdd(&g_loss, sred[0]);
}

__global__ void k_fin1(const float* __restrict__ cs, float* __restrict__ dout) {
    __shared__ float sn[1024];
    __shared__ float sp[1024];
    int t = threadIdx.x;
    float ln = 0.f, lp = 0.f;
    for (int j = t; j < N_CODES; j += 1024) {
        float es  = g_enc_sum[j];
        float ncs = cs[j] * DECAYF + OMDF * es;
        dout[OFF_CS + j] = ncs;
        ln += ncs;
        float pr = es * (1.0f / (float)N_VECS);
        lp += pr * logf(pr + 1e-10f);
    }
    sn[t] = ln; sp[t] = lp;
    __syncthreads();
    for (int s = 512; s; s >>= 1) {
        if (t < s) { sn[t] += sn[t + s]; sp[t] += sp[t + s]; }
        __syncthreads();
    }
    if (t == 0) {
        g_n = sn[0];
        dout[OFF_PERP] = expf(-sp[0]);
        dout[OFF_LOSS] = g_loss * (BETAF / (float)TOTAL_ELEMS);
    }
}

__global__ void k_fin2(const float* __restrict__ ea, float* __restrict__ dout) {
    int i = blockIdx.x * blockDim.x + threadIdx.x;
    if (i >= N_CODES * E_DIM) return;
    int code = i >> 8;
    float nea = ea[i] * DECAYF + OMDF * g_embed_sum[i];
    dout[OFF_EA + i] = nea;
    float ncs = dout[OFF_CS + code];
    float n = g_n;
    float sm = (ncs + EPSF) / (n + (float)N_CODES * EPSF) * n;
    dout[OFF_EMB + i] = nea / sm;
}

// ---------------------------------------------------------------- launch
extern "C" void kernel_launch(void* const* d_in, const int* in_sizes, int n_in,
                              void* d_out, int out_size) {
    const float* z   = (const float*)d_in[0];
    const float* emb = (const float*)d_in[1];
    const float* cs  = (const float*)d_in[2];
    const float* ea  = (const float*)d_in[3];
    float* out = (float*)d_out;

    cudaFuncSetAttribute(k_mma, cudaFuncAttributeMaxDynamicSharedMemorySize, SMEM_TOTAL);

    k_zero<<<1024, 512>>>();
    k_enorm<<<512, 256>>>(emb);
    k_split_z<<<dim3(32, 8, 16), dim3(32, 8)>>>(z);
    k_mma<<<N_VECS / M_BLK, 256, SMEM_TOTAL>>>();
    k_refine<<<N_VECS / 8, 256>>>(emb, out);
    k_gather<<<4096, 256>>>(z, emb, out);
    k_fin1<<<1, 1024>>>(cs, out);
    k_fin2<<<4096, 256>>>(ea, out);
}